// round 6
// baseline (speedup 1.0000x reference)
#include <cuda_runtime.h>
#include <cuda_bf16.h>
#include <math.h>
#include <stdint.h>

#define Bz   8
#define Sz   512
#define Dm   512
#define Hn   8
#define DKh  64
#define Lz   6
#define DFFz 2048
#define OUTz 1000
#define NEGV (-1e9f)

// ---------------- scratch (device globals) ----------------
__device__ float g_e[Bz*Sz*Dm];
__device__ __nv_bfloat16 g_ehi[Bz*Sz*Dm], g_elo[Bz*Sz*Dm];
__device__ __nv_bfloat16 g_qkvh[3*Bz*Sz*Dm], g_qkvl[3*Bz*Sz*Dm];
__device__ float g_kvf[2*Bz*Sz*Dm];
__device__ float g_sc[(size_t)Bz*Hn*Sz*Sz];
__device__ __nv_bfloat16 g_schi[(size_t)Bz*Hn*Sz*Sz], g_sclo[(size_t)Bz*Hn*Sz*Sz];
__device__ float g_attn[Bz*Sz*Dm];
__device__ __nv_bfloat16 g_hhi[Bz*Sz*DFFz], g_hlo[Bz*Sz*DFFz];
__device__ float g_t[Bz*Sz*Dm];
__device__ float g_d[Bz*Dm];
__device__ float g_dq[Bz*Dm];
__device__ float g_dt[Bz*Dm];
__device__ float g_dh[Bz*DFFz];
// split weights in original [K,N] layout
__device__ __nv_bfloat16 g_wqkvh[Lz*3*Dm*Dm], g_wqkvl[Lz*3*Dm*Dm];
__device__ __nv_bfloat16 g_wf1h[Lz*Dm*DFFz],  g_wf1l[Lz*Dm*DFFz];
__device__ __nv_bfloat16 g_wf2h[Lz*DFFz*Dm],  g_wf2l[Lz*DFFz*Dm];
__device__ __nv_bfloat16 g_wd2h[Lz*3*Dm*Dm],  g_wd2l[Lz*3*Dm*Dm];

// ---------------- helpers ----------------
__device__ __forceinline__ void cpa16(void* dst, const void* src) {
    uint32_t d = (uint32_t)__cvta_generic_to_shared(dst);
    asm volatile("cp.async.ca.shared.global [%0], [%1], 16;\n" :: "r"(d), "l"(src));
}
#define CP_COMMIT() asm volatile("cp.async.commit_group;\n" ::: "memory")
__device__ __forceinline__ void ldsm4(uint32_t& r0, uint32_t& r1, uint32_t& r2, uint32_t& r3,
                                      const void* p) {
    uint32_t a = (uint32_t)__cvta_generic_to_shared(p);
    asm volatile("ldmatrix.sync.aligned.m8n8.x4.shared.b16 {%0,%1,%2,%3}, [%4];\n"
                 : "=r"(r0), "=r"(r1), "=r"(r2), "=r"(r3) : "r"(a));
}
__device__ __forceinline__ void ldsm4t(uint32_t& r0, uint32_t& r1, uint32_t& r2, uint32_t& r3,
                                       const void* p) {
    uint32_t a = (uint32_t)__cvta_generic_to_shared(p);
    asm volatile("ldmatrix.sync.aligned.m8n8.x4.trans.shared.b16 {%0,%1,%2,%3}, [%4];\n"
                 : "=r"(r0), "=r"(r1), "=r"(r2), "=r"(r3) : "r"(a));
}
__device__ __forceinline__ void mma_bf16(float c[4], const uint32_t a[4], const uint32_t b[2]) {
    asm volatile(
        "mma.sync.aligned.m16n8k16.row.col.f32.bf16.bf16.f32 "
        "{%0,%1,%2,%3}, {%4,%5,%6,%7}, {%8,%9}, {%0,%1,%2,%3};\n"
        : "+f"(c[0]), "+f"(c[1]), "+f"(c[2]), "+f"(c[3])
        : "r"(a[0]), "r"(a[1]), "r"(a[2]), "r"(a[3]), "r"(b[0]), "r"(b[1]));
}

// ---------------- split f32 -> bf16 hi/lo ----------------
__global__ void splitk(const float* __restrict__ src, __nv_bfloat16* __restrict__ hi,
                       __nv_bfloat16* __restrict__ lo, int n) {
    int i = blockIdx.x*blockDim.x + threadIdx.x;
    if (i >= n) return;
    float v = src[i];
    __nv_bfloat16 h = __float2bfloat16(v);
    hi[i] = h;
    lo[i] = __float2bfloat16(v - __bfloat162float(h));
}

// ---------------- embedding + PE ----------------
__global__ void embed_enc(const int* __restrict__ x, const float* __restrict__ emb,
                          float* __restrict__ e, __nv_bfloat16* __restrict__ ehi,
                          __nv_bfloat16* __restrict__ elo) {
    int idx = blockIdx.x*blockDim.x + threadIdx.x;
    if (idx >= Bz*Sz*Dm) return;
    int d  = idx % Dm;
    int bs = idx / Dm;
    int s  = bs % Sz;
    int tok = x[bs];
    float div = exp2f(-(float)(d & ~1) * (13.287712379549449f / (float)Dm));
    float arg = (float)s * div;
    float pe = (d & 1) ? cosf(arg) : sinf(arg);
    float v = emb[tok*Dm + d] * 22.627416997969522f + pe;
    e[idx] = v;
    __nv_bfloat16 h = __float2bfloat16(v);
    ehi[idx] = h;
    elo[idx] = __float2bfloat16(v - __bfloat162float(h));
}

__global__ void embed_dec(const int* __restrict__ tgt, const float* __restrict__ emb,
                          float* __restrict__ o) {
    int idx = blockIdx.x*blockDim.x + threadIdx.x;
    if (idx >= Bz*Dm) return;
    int d = idx % Dm;
    int b = idx / Dm;
    float pe = (d & 1) ? 1.f : 0.f;
    o[idx] = emb[tgt[b]*Dm + d] * 22.627416997969522f + pe;
}

// ============ 3-stage pipelined mma.sync GEMM (bf16x3, big tiles) ===========
// C[M,N] = A[M,K] @ B; A as bf16 hi/lo [M,K].
// TB=0: B is [K,N] (ldmatrix.trans). TB=1: B is [N,K] (direct).
// BM=128; BN_=128 -> 256 thr (warps 2m x 4n); BN_=64 -> 128 thr (2m x 2n).
// Warp tile 64x32. 48 HMMA / 12 LDSM per warp-k16.
// EPI: 0=+bias, 1=+bias+relu, 2=*0.125&(==0->NEGV), 3=none.
// WMODE bit0: f32 C; bit1: split Chi/Clo.
template<int BN_, int EPI, int TB, int WMODE>
__global__ void __launch_bounds__(BN_ == 128 ? 256 : 128, 1)
gemm_mma(const __nv_bfloat16* __restrict__ Agh, const __nv_bfloat16* __restrict__ Agl,
         const __nv_bfloat16* __restrict__ Bgh, const __nv_bfloat16* __restrict__ Bgl,
         const float* __restrict__ bias,
         float* __restrict__ C, __nv_bfloat16* __restrict__ Chi,
         __nv_bfloat16* __restrict__ Clo,
         int K, int lda, int ldb, int ldc,
         int zdiv, long long sA1, long long sA2, long long sB1, long long sB2,
         long long sC1, long long sC2, long long sBias) {
    constexpr int NT   = (BN_ == 128) ? 256 : 128;
    constexpr int ASTG = 128 * 40;                         // elems per A stage
    constexpr int BROW = TB ? BN_ : 32;
    constexpr int BLD  = TB ? 40 : (BN_ + 8);
    constexpr int BSTG = BROW * BLD;

    extern __shared__ __nv_bfloat16 sm[];
    __nv_bfloat16* Ah = sm;
    __nv_bfloat16* Al = Ah + 3*ASTG;
    __nv_bfloat16* Bh = Al + 3*ASTG;
    __nv_bfloat16* Bl = Bh + 3*BSTG;

    int z = blockIdx.z, z1 = z / zdiv, z2 = z % zdiv;
    const __nv_bfloat16* Abh = Agh + z1*sA1 + z2*sA2;
    const __nv_bfloat16* Abl = Agl + z1*sA1 + z2*sA2;
    const __nv_bfloat16* Bbh = Bgh + z1*sB1 + z2*sB2;
    const __nv_bfloat16* Bbl = Bgl + z1*sB1 + z2*sB2;
    long long coff = z1*sC1 + z2*sC2;

    int m0 = blockIdx.y * 128, n0 = blockIdx.x * BN_;
    int tid = threadIdx.x, lane = tid & 31, wid = tid >> 5;
    int wm = wid & 1, wn = wid >> 1;
    int gid = lane >> 2, tig = lane & 3;

    auto load_stage = [&](int st, int kt) {
        int k0 = kt * 32;
        // A planes: 128 rows x 4 chunks of 8 bf16
        for (int idx = tid; idx < 512; idx += NT) {
            int r = idx >> 2, c = (idx & 3) * 8;
            int so = st*ASTG + r*40 + c;
            const __nv_bfloat16* s1 = Abh + (size_t)(m0 + r)*lda + k0 + c;
            const __nv_bfloat16* s2 = Abl + (size_t)(m0 + r)*lda + k0 + c;
            cpa16(Ah + so, s1);
            cpa16(Al + so, s2);
        }
        if (TB) {   // B [N,K]: BN_ rows x 4 chunks
            for (int idx = tid; idx < BN_*4; idx += NT) {
                int r = idx >> 2, c = (idx & 3) * 8;
                int so = st*BSTG + r*40 + c;
                cpa16(Bh + so, Bbh + (size_t)(n0 + r)*ldb + k0 + c);
                cpa16(Bl + so, Bbl + (size_t)(n0 + r)*ldb + k0 + c);
            }
        } else {    // B [K,N]: 32 rows x BN_/8 chunks
            constexpr int CH = BN_ / 8;
            for (int idx = tid; idx < 32*CH; idx += NT) {
                int r = idx / CH, c = (idx % CH) * 8;
                int so = st*BSTG + r*BLD + c;
                cpa16(Bh + so, Bbh + (size_t)(k0 + r)*ldb + n0 + c);
                cpa16(Bl + so, Bbl + (size_t)(k0 + r)*ldb + n0 + c);
            }
        }
    };

    float acc[4][4][4] = {};
    const int KT = K >> 5;

    load_stage(0, 0); CP_COMMIT();
    if (KT > 1) { load_stage(1, 1); CP_COMMIT(); }
    if (KT > 1) asm volatile("cp.async.wait_group 1;\n" ::: "memory");
    else        asm volatile("cp.async.wait_group 0;\n" ::: "memory");
    __syncthreads();

    for (int c = 0; c < KT; c++) {
        int st = c % 3;
        const __nv_bfloat16* a_h = Ah + st*ASTG;
        const __nv_bfloat16* a_l = Al + st*ASTG;
        const __nv_bfloat16* b_h = Bh + st*BSTG;
        const __nv_bfloat16* b_l = Bl + st*BSTG;

#pragma unroll
        for (int kk = 0; kk < 2; kk++) {
            int kc = kk*16 + ((lane >> 4) << 3);
            uint32_t ah[4][4], al[4][4], bh[4][2], bl[4][2];
#pragma unroll
            for (int mi = 0; mi < 4; mi++) {
                int ar = wm*64 + mi*16 + (lane & 15);
                ldsm4(ah[mi][0], ah[mi][1], ah[mi][2], ah[mi][3], a_h + ar*40 + kc);
                ldsm4(al[mi][0], al[mi][1], al[mi][2], al[mi][3], a_l + ar*40 + kc);
            }
#pragma unroll
            for (int ng = 0; ng < 2; ng++) {
                uint32_t r0, r1, r2, r3;
                if (TB) {
                    int br = wn*32 + ng*16 + (lane & 15);
                    ldsm4(r0, r1, r2, r3, b_h + br*40 + kc);
                    bh[ng*2  ][0] = r0; bh[ng*2  ][1] = r2;
                    bh[ng*2+1][0] = r1; bh[ng*2+1][1] = r3;
                    ldsm4(r0, r1, r2, r3, b_l + br*40 + kc);
                    bl[ng*2  ][0] = r0; bl[ng*2  ][1] = r2;
                    bl[ng*2+1][0] = r1; bl[ng*2+1][1] = r3;
                } else {
                    int rr = kk*16 + ((lane >> 4) << 3) + (lane & 7);
                    int cc = wn*32 + ng*16 + (((lane >> 3) & 1) << 3);
                    ldsm4t(r0, r1, r2, r3, b_h + rr*BLD + cc);
                    bh[ng*2  ][0] = r0; bh[ng*2  ][1] = r2;
                    bh[ng*2+1][0] = r1; bh[ng*2+1][1] = r3;
                    ldsm4t(r0, r1, r2, r3, b_l + rr*BLD + cc);
                    bl[ng*2  ][0] = r0; bl[ng*2  ][1] = r2;
                    bl[ng*2+1][0] = r1; bl[ng*2+1][1] = r3;
                }
            }
            // hh, hl, lh: same-acc RAW chains spaced 16 apart
#pragma unroll
            for (int mi = 0; mi < 4; mi++)
#pragma unroll
                for (int ni = 0; ni < 4; ni++) mma_bf16(acc[mi][ni], ah[mi], bh[ni]);
#pragma unroll
            for (int mi = 0; mi < 4; mi++)
#pragma unroll
                for (int ni = 0; ni < 4; ni++) mma_bf16(acc[mi][ni], ah[mi], bl[ni]);
#pragma unroll
            for (int mi = 0; mi < 4; mi++)
#pragma unroll
                for (int ni = 0; ni < 4; ni++) mma_bf16(acc[mi][ni], al[mi], bh[ni]);
        }

        if (c + 2 < KT) {
            load_stage((c + 2) % 3, c + 2);
            CP_COMMIT();
            asm volatile("cp.async.wait_group 1;\n" ::: "memory");
            __syncthreads();
        } else if (c + 1 < KT) {
            asm volatile("cp.async.wait_group 0;\n" ::: "memory");
            __syncthreads();
        }
    }

    // ---- epilogue ----
    const float* biasb = (EPI <= 1) ? bias + (long long)z * sBias : nullptr;
#pragma unroll
    for (int mi = 0; mi < 4; mi++)
#pragma unroll
        for (int ni = 0; ni < 4; ni++) {
            int row = m0 + wm*64 + mi*16 + gid;
            int col = n0 + wn*32 + ni*8 + tig*2;
#pragma unroll
            for (int e2 = 0; e2 < 4; e2++) {
                int r  = row + (e2 >> 1)*8;
                int cc = col + (e2 & 1);
                float v = acc[mi][ni][e2];
                if (EPI == 0 || EPI == 1) v += biasb[cc];
                if (EPI == 1) v = fmaxf(v, 0.f);
                if (EPI == 2) { v *= 0.125f; if (v == 0.f) v = NEGV; }
                size_t idx = (size_t)(coff + (long long)r*ldc + cc);
                if (WMODE & 1) C[idx] = v;
                if (WMODE & 2) {
                    __nv_bfloat16 h = __float2bfloat16(v);
                    Chi[idx] = h;
                    Clo[idx] = __float2bfloat16(v - __bfloat162float(h));
                }
            }
        }
}

// ---------------- row softmax over 512 -> split bf16 ----------------
__global__ void softmax512(const float* __restrict__ s, __nv_bfloat16* __restrict__ phi,
                           __nv_bfloat16* __restrict__ plo) {
    size_t row = blockIdx.x;
    const float* p = s + row * Sz;
    int tid = threadIdx.x;                 // 128
    float4 v = *(const float4*)&p[tid*4];
    float mx = fmaxf(fmaxf(v.x, v.y), fmaxf(v.z, v.w));
#pragma unroll
    for (int o = 16; o; o >>= 1) mx = fmaxf(mx, __shfl_xor_sync(0xffffffffu, mx, o));
    __shared__ float sm[4];
    if ((tid & 31) == 0) sm[tid >> 5] = mx;
    __syncthreads();
    mx = fmaxf(fmaxf(sm[0], sm[1]), fmaxf(sm[2], sm[3]));
    v.x = expf(v.x - mx); v.y = expf(v.y - mx);
    v.z = expf(v.z - mx); v.w = expf(v.w - mx);
    float sum = v.x + v.y + v.z + v.w;
#pragma unroll
    for (int o = 16; o; o >>= 1) sum += __shfl_xor_sync(0xffffffffu, sum, o);
    __shared__ float ss[4];
    if ((tid & 31) == 0) ss[tid >> 5] = sum;
    __syncthreads();
    sum = ss[0] + ss[1] + ss[2] + ss[3];
    float inv = 1.f / sum;
    float vv[4] = {v.x*inv, v.y*inv, v.z*inv, v.w*inv};
    __nv_bfloat16 hh[4], ll[4];
#pragma unroll
    for (int j = 0; j < 4; j++) {
        hh[j] = __float2bfloat16(vv[j]);
        ll[j] = __float2bfloat16(vv[j] - __bfloat162float(hh[j]));
    }
    *(uint2*)&phi[row*Sz + tid*4] = *(uint2*)hh;
    *(uint2*)&plo[row*Sz + tid*4] = *(uint2*)ll;
}

// ---------------- out = LayerNorm(a + res) (+ optional split) ---------------
template<int SPLIT>
__global__ void add_ln(const float* __restrict__ a, const float* __restrict__ res,
                       const float* __restrict__ g, const float* __restrict__ beta,
                       float* __restrict__ out, __nv_bfloat16* __restrict__ ohi,
                       __nv_bfloat16* __restrict__ olo) {
    size_t row = blockIdx.x;
    int tid = threadIdx.x;
    int c = tid * 4;
    float4 av = *(const float4*)&a[row*Dm + c];
    float4 rv = *(const float4*)&res[row*Dm + c];
    float4 x;
    x.x = av.x + rv.x; x.y = av.y + rv.y; x.z = av.z + rv.z; x.w = av.w + rv.w;
    float s  = x.x + x.y + x.z + x.w;
    float s2 = x.x*x.x + x.y*x.y + x.z*x.z + x.w*x.w;
#pragma unroll
    for (int o = 16; o; o >>= 1) {
        s  += __shfl_xor_sync(0xffffffffu, s,  o);
        s2 += __shfl_xor_sync(0xffffffffu, s2, o);
    }
    __shared__ float sm[4], sq[4];
    if ((tid & 31) == 0) { sm[tid>>5] = s; sq[tid>>5] = s2; }
    __syncthreads();
    s  = sm[0] + sm[1] + sm[2] + sm[3];
    s2 = sq[0] + sq[1] + sq[2] + sq[3];
    float mean = s * (1.f/Dm);
    float var  = s2 * (1.f/Dm) - mean*mean;
    float inv  = rsqrtf(var + 1e-5f);
    float4 gv = *(const float4*)&g[c];
    float4 bv = *(const float4*)&beta[c];
    float y[4];
    y[0] = (x.x - mean)*inv*gv.x + bv.x;
    y[1] = (x.y - mean)*inv*gv.y + bv.y;
    y[2] = (x.z - mean)*inv*gv.z + bv.z;
    y[3] = (x.w - mean)*inv*gv.w + bv.w;
    *(float4*)&out[row*Dm + c] = *(float4*)y;
    if (SPLIT) {
        __nv_bfloat16 hh[4], ll[4];
#pragma unroll
        for (int j = 0; j < 4; j++) {
            hh[j] = __float2bfloat16(y[j]);
            ll[j] = __float2bfloat16(y[j] - __bfloat162float(hh[j]));
        }
        *(uint2*)&ohi[row*Dm + c] = *(uint2*)hh;
        *(uint2*)&olo[row*Dm + c] = *(uint2*)ll;
    }
}

// ---------------- decoder cross-attention (Sq=1, f32) ----------------
__global__ void cross_attn(const float* __restrict__ q, const float* __restrict__ k,
                           const float* __restrict__ v, float* __restrict__ o) {
    int h = blockIdx.x, b = blockIdx.y;
    __shared__ float qv[64];
    __shared__ float p[512];
    __shared__ float red[8];
    int tid = threadIdx.x;
    if (tid < 64) qv[tid] = q[b*Dm + h*DKh + tid];
    __syncthreads();
    float sc[2];
    float lmax = -INFINITY;
#pragma unroll
    for (int it = 0; it < 2; it++) {
        int j = tid + it*256;
        const float* kp = &k[(size_t)(b*Sz + j)*Dm + h*DKh];
        float s = 0.f;
#pragma unroll
        for (int c = 0; c < 64; c++) s += qv[c] * kp[c];
        s *= 0.125f;
        if (s == 0.f) s = NEGV;
        sc[it] = s;
        lmax = fmaxf(lmax, s);
    }
#pragma unroll
    for (int off = 16; off; off >>= 1) lmax = fmaxf(lmax, __shfl_xor_sync(0xffffffffu, lmax, off));
    if ((tid & 31) == 0) red[tid >> 5] = lmax;
    __syncthreads();
    float mx = red[0];
#pragma unroll
    for (int w = 1; w < 8; w++) mx = fmaxf(mx, red[w]);
    __syncthreads();
    float lsum = 0.f;
#pragma unroll
    for (int it = 0; it < 2; it++) {
        float e = expf(sc[it] - mx);
        p[tid + it*256] = e;
        lsum += e;
    }
#pragma unroll
    for (int off = 16; off; off >>= 1) lsum += __shfl_xor_sync(0xffffffffu, lsum, off);
    if ((tid & 31) == 0) red[tid >> 5] = lsum;
    __syncthreads();
    float sum = red[0] + red[1] + red[2] + red[3] + red[4] + red[5] + red[6] + red[7];
    float inv = 1.f / sum;
    int warp = tid >> 5, lane = tid & 31;
#pragma unroll
    for (int dd = 0; dd < 8; dd++) {
        int d = warp*8 + dd;
        float acc = 0.f;
        for (int j = lane; j < Sz; j += 32)
            acc += p[j] * v[(size_t)(b*Sz + j)*Dm + h*DKh + d];
#pragma unroll
        for (int off = 16; off; off >>= 1) acc += __shfl_xor_sync(0xffffffffu, acc, off);
        if (lane == 0) o[b*Dm + h*DKh + d] = acc * inv;
    }
}

// ---------------- tiny-M (M=8) GEMM for decoder ----------------
__global__ void gemm8(const float* __restrict__ A, const float* __restrict__ W,
                      const float* __restrict__ bias, float* __restrict__ C,
                      int K, int N, int relu) {
    int col = blockIdx.x*blockDim.x + threadIdx.x;
    if (col >= N) return;
    float acc[8] = {};
    for (int k = 0; k < K; k++) {
        float wv = W[(size_t)k*N + col];
#pragma unroll
        for (int r = 0; r < 8; r++) acc[r] += A[r*K + k] * wv;
    }
    float bv = bias[col];
#pragma unroll
    for (int r = 0; r < 8; r++) {
        float val = acc[r] + bv;
        if (relu) val = fmaxf(val, 0.f);
        C[r*N + col] = val;
    }
}

// ---------------- host orchestration ----------------
extern "C" void kernel_launch(void* const* d_in, const int* in_sizes, int n_in,
                              void* d_out, int out_size) {
    const int*   x        = (const int*)d_in[0];
    const int*   tgt      = (const int*)d_in[1];
    const float* in_emb   = (const float*)d_in[2];
    const float* out_emb  = (const float*)d_in[3];
    const float* enc_qkv_w = (const float*)d_in[4];
    const float* enc_qkv_b = (const float*)d_in[5];
    const float* enc_ln1_g = (const float*)d_in[6];
    const float* enc_ln1_b = (const float*)d_in[7];
    const float* enc_ffn1_w = (const float*)d_in[8];
    const float* enc_ffn1_b = (const float*)d_in[9];
    const float* enc_ffn2_w = (const float*)d_in[10];
    const float* enc_ffn2_b = (const float*)d_in[11];
    const float* enc_ln2_g = (const float*)d_in[12];
    const float* enc_ln2_b = (const float*)d_in[13];
    const float* dec_qkv1_w = (const float*)d_in[14];
    const float* dec_qkv1_b = (const float*)d_in[15];
    const float* dec_ln1_g = (const float*)d_in[16];
    const float* dec_ln1_b = (const float*)d_in[17];
    const float* dec_qkv2_w = (const float*)d_in[18];
    const float* dec_qkv2_b = (const float*)d_in[19];
    const float* dec_ln2_g = (const float*)d_in[20];
    const float* dec_ln2_b = (const float*)d_in[21];
    const float* dec_ffn1_w = (const float*)d_in[22];
    const float* dec_ffn1_b = (const float*)d_in[23];
    const float* dec_ffn2_w = (const float*)d_in[24];
    const float* dec_ffn2_b = (const float*)d_in[25];
    const float* dec_ln3_g = (const float*)d_in[26];
    const float* dec_ln3_b = (const float*)d_in[27];
    const float* out_w = (const float*)d_in[28];
    const float* out_b = (const float*)d_in[29];

    float *e, *sc, *attn, *tbuf, *dbuf, *dq, *dt, *dh, *kvf;
    __nv_bfloat16 *ehi, *elo, *qkvh, *qkvl, *schi, *sclo, *hhi, *hlo;
    __nv_bfloat16 *wqkvh, *wqkvl, *wf1h, *wf1l, *wf2h, *wf2l, *wd2h, *wd2l;
    cudaGetSymbolAddress((void**)&e,    g_e);
    cudaGetSymbolAddress((void**)&ehi,  g_ehi);
    cudaGetSymbolAddress((void**)&elo,  g_elo);
    cudaGetSymbolAddress((void**)&qkvh, g_qkvh);
    cudaGetSymbolAddress((void**)&qkvl, g_qkvl);
    cudaGetSymbolAddress((void**)&kvf,  g_kvf);
    cudaGetSymbolAddress((void**)&sc,   g_sc);
    cudaGetSymbolAddress((void**)&schi, g_schi);
    cudaGetSymbolAddress((void**)&sclo, g_sclo);
    cudaGetSymbolAddress((void**)&attn, g_attn);
    cudaGetSymbolAddress((void**)&hhi,  g_hhi);
    cudaGetSymbolAddress((void**)&hlo,  g_hlo);
    cudaGetSymbolAddress((void**)&tbuf, g_t);
    cudaGetSymbolAddress((void**)&dbuf, g_d);
    cudaGetSymbolAddress((void**)&dq,   g_dq);
    cudaGetSymbolAddress((void**)&dt,   g_dt);
    cudaGetSymbolAddress((void**)&dh,   g_dh);
    cudaGetSymbolAddress((void**)&wqkvh, g_wqkvh);
    cudaGetSymbolAddress((void**)&wqkvl, g_wqkvl);
    cudaGetSymbolAddress((void**)&wf1h, g_wf1h);
    cudaGetSymbolAddress((void**)&wf1l, g_wf1l);
    cudaGetSymbolAddress((void**)&wf2h, g_wf2h);
    cudaGetSymbolAddress((void**)&wf2l, g_wf2l);
    cudaGetSymbolAddress((void**)&wd2h, g_wd2h);
    cudaGetSymbolAddress((void**)&wd2l, g_wd2l);

    const int M = Bz*Sz;            // 4096
    const long long DD = (long long)Dm*Dm;
    const long long MD = (long long)M*Dm;
    const long long SS = (long long)Sz*Sz;
    const long long SDm = (long long)Sz*Dm;

    // smem sizes (bytes): A = 2 planes * 3 stages * 128*40 * 2B = 61440
    const int SM_TB0_128 = 61440 + 2*3*32*136*2;   // 113664
    const int SM_TB1_128 = 61440 + 2*3*128*40*2;   // 122880
    const int SM_TB0_64  = 61440 + 2*3*32*72*2;    //  89088
    cudaFuncSetAttribute(gemm_mma<128,0,0,2>, cudaFuncAttributeMaxDynamicSharedMemorySize, SM_TB0_128);
    cudaFuncSetAttribute(gemm_mma<128,2,1,1>, cudaFuncAttributeMaxDynamicSharedMemorySize, SM_TB1_128);
    cudaFuncSetAttribute(gemm_mma<64,3,0,1>,  cudaFuncAttributeMaxDynamicSharedMemorySize, SM_TB0_64);
    cudaFuncSetAttribute(gemm_mma<128,1,0,2>, cudaFuncAttributeMaxDynamicSharedMemorySize, SM_TB0_128);
    cudaFuncSetAttribute(gemm_mma<128,0,0,1>, cudaFuncAttributeMaxDynamicSharedMemorySize, SM_TB0_128);

    // ---- split weights once per launch (original [K,N] layout) ----
    {
        int n1 = Lz*3*Dm*Dm;
        splitk<<<(n1+255)/256, 256>>>(enc_qkv_w, wqkvh, wqkvl, n1);
        int n2 = Lz*Dm*DFFz;
        splitk<<<(n2+255)/256, 256>>>(enc_ffn1_w, wf1h, wf1l, n2);
        splitk<<<(n2+255)/256, 256>>>(enc_ffn2_w, wf2h, wf2l, n2);
        splitk<<<(n1+255)/256, 256>>>(dec_qkv2_w, wd2h, wd2l, n1);
    }

    // ---------------- encoder ----------------
    embed_enc<<<(Bz*Sz*Dm + 255)/256, 256>>>(x, in_emb, e, ehi, elo);
    for (int i = 0; i < Lz; i++) {
        // fused QKV: z=3 weights; split-plane output
        gemm_mma<128,0,0,2><<<dim3(Dm/128, M/128, 3), 256, SM_TB0_128>>>(
            ehi, elo, wqkvh + (size_t)i*3*DD, wqkvl + (size_t)i*3*DD,
            enc_qkv_b + (size_t)i*3*Dm, nullptr, qkvh, qkvl,
            Dm, Dm, Dm, Dm,
            1, 0, 0, DD, 0, MD, 0, Dm);
        // scores: per (b,h), S = Q K^T / 8 + quirky mask (f32 out)
        gemm_mma<128,2,1,1><<<dim3(Sz/128, Sz/128, Bz*Hn), 256, SM_TB1_128>>>(
            qkvh, qkvl, qkvh + MD, qkvl + MD, nullptr, sc, nullptr, nullptr,
            DKh, Dm, Dm, Sz,
            Hn, SDm, DKh, SDm, DKh, (long long)Hn*SS, SS, 0);
        softmax512<<<Bz*Hn*Sz, 128>>>(sc, schi, sclo);
        // PV: per (b,h), O = P V (V split planes in [s][d] = [K][N])
        gemm_mma<64,3,0,1><<<dim3(1, Sz/128, Bz*Hn), 128, SM_TB0_64>>>(
            schi, sclo, qkvh + 2*MD, qkvl + 2*MD, nullptr, attn, nullptr, nullptr,
            Sz, Sz, Dm, Dm,
            Hn, (long long)Hn*SS, SS, SDm, DKh, SDm, DKh, 0);
        add_ln<1><<<M, 128>>>(attn, e, enc_ln1_g + i*Dm, enc_ln1_b + i*Dm, e, ehi, elo);
        // FFN1 (+relu), split out
        gemm_mma<128,1,0,2><<<dim3(DFFz/128, M/128, 1), 256, SM_TB0_128>>>(
            ehi, elo, wf1h + (size_t)i*Dm*DFFz, wf1l + (size_t)i*Dm*DFFz,
            enc_ffn1_b + (size_t)i*DFFz, nullptr, hhi, hlo,
            Dm, Dm, DFFz, DFFz,
            1, 0, 0, 0, 0, 0, 0, 0);
        // FFN2 (f32 out)
        gemm_mma<128,0,0,1><<<dim3(Dm/128, M/128, 1), 256, SM_TB0_128>>>(
            hhi, hlo, wf2h + (size_t)i*DFFz*Dm, wf2l + (size_t)i*DFFz*Dm,
            enc_ffn2_b + (size_t)i*Dm, tbuf, nullptr, nullptr,
            DFFz, DFFz, Dm, Dm,
            1, 0, 0, 0, 0, 0, 0, 0);
        add_ln<1><<<M, 128>>>(tbuf, e, enc_ln2_g + i*Dm, enc_ln2_b + i*Dm, e, ehi, elo);
    }

    // ---------------- decoder (seq len 1; self-attn == V projection) --------
    embed_dec<<<(Bz*Dm + 255)/256, 256>>>(tgt, out_emb, dbuf);
    for (int i = 0; i < Lz; i++) {
        gemm8<<<(Dm+127)/128, 128>>>(dbuf, dec_qkv1_w + (size_t)(i*3+2)*DD, dec_qkv1_b + (i*3+2)*Dm, dt, Dm, Dm, 0);
        add_ln<0><<<Bz, 128>>>(dt, dbuf, dec_ln1_g + i*Dm, dec_ln1_b + i*Dm, dbuf, nullptr, nullptr);
        // cross-attn: q from decoder; K,V projections of encoder output (z=2)
        gemm8<<<(Dm+127)/128, 128>>>(dbuf, dec_qkv2_w + (size_t)(i*3+0)*DD, dec_qkv2_b + (i*3+0)*Dm, dq, Dm, Dm, 0);
        gemm_mma<128,0,0,1><<<dim3(Dm/128, M/128, 2), 256, SM_TB0_128>>>(
            ehi, elo, wd2h + (size_t)(i*3+1)*DD, wd2l + (size_t)(i*3+1)*DD,
            dec_qkv2_b + (size_t)(i*3+1)*Dm, kvf, nullptr, nullptr,
            Dm, Dm, Dm, Dm,
            1, 0, 0, DD, 0, MD, 0, Dm);
        cross_attn<<<dim3(Hn, Bz), 256>>>(dq, kvf /*K*/, kvf + MD /*V*/, dt);
        add_ln<0><<<Bz, 128>>>(dt, dbuf, dec_ln2_g + i*Dm, dec_ln2_b + i*Dm, dbuf, nullptr, nullptr);
        gemm8<<<(DFFz+127)/128, 128>>>(dbuf, dec_ffn1_w + (size_t)i*Dm*DFFz, dec_ffn1_b + i*DFFz, dh, Dm, DFFz, 1);
        gemm8<<<(Dm+127)/128, 128>>>(dh, dec_ffn2_w + (size_t)i*DFFz*Dm, dec_ffn2_b + i*Dm, dt, DFFz, Dm, 0);
        add_ln<0><<<Bz, 128>>>(dt, dbuf, dec_ln3_g + i*Dm, dec_ln3_b + i*Dm, dbuf, nullptr, nullptr);
    }

    // output projection -> d_out [8,1,1000]
    gemm8<<<(OUTz+127)/128, 128>>>(dbuf, out_w, out_b, (float*)d_out, Dm, OUTz, 0);
    (void)in_sizes; (void)n_in; (void)out_size;
}

// round 7
// speedup vs baseline: 2.2004x; 2.2004x over previous
#include <cuda_runtime.h>
#include <cuda_bf16.h>
#include <math.h>
#include <stdint.h>

#define Bz   8
#define Sz   512
#define Dm   512
#define Hn   8
#define DKh  64
#define Lz   6
#define DFFz 2048
#define OUTz 1000
#define NEGV (-1e9f)

// ---------------- scratch (device globals) ----------------
__device__ float g_e[Bz*Sz*Dm];
__device__ __nv_bfloat16 g_ehi[Bz*Sz*Dm], g_elo[Bz*Sz*Dm];
__device__ __nv_bfloat16 g_qkvh[3*Bz*Sz*Dm], g_qkvl[3*Bz*Sz*Dm];
__device__ float g_kvf[2*Bz*Sz*Dm];
__device__ __nv_bfloat16 g_schi[(size_t)Bz*Hn*Sz*Sz], g_sclo[(size_t)Bz*Hn*Sz*Sz];
__device__ float g_attn[Bz*Sz*Dm];
__device__ __nv_bfloat16 g_hhi[Bz*Sz*DFFz], g_hlo[Bz*Sz*DFFz];
__device__ float g_t[Bz*Sz*Dm];
__device__ float g_d[Bz*Dm];
__device__ float g_dq[Bz*Dm];
__device__ float g_dt[Bz*Dm];
__device__ float g_dh[Bz*DFFz];
// split weights in original [K,N] layout
__device__ __nv_bfloat16 g_wqkvh[Lz*3*Dm*Dm], g_wqkvl[Lz*3*Dm*Dm];
__device__ __nv_bfloat16 g_wf1h[Lz*Dm*DFFz],  g_wf1l[Lz*Dm*DFFz];
__device__ __nv_bfloat16 g_wf2h[Lz*DFFz*Dm],  g_wf2l[Lz*DFFz*Dm];
__device__ __nv_bfloat16 g_wd2h[Lz*3*Dm*Dm],  g_wd2l[Lz*3*Dm*Dm];

// ---------------- helpers ----------------
__device__ __forceinline__ void cpa16(void* dst, const void* src) {
    uint32_t d = (uint32_t)__cvta_generic_to_shared(dst);
    asm volatile("cp.async.ca.shared.global [%0], [%1], 16;\n" :: "r"(d), "l"(src));
}
#define CP_COMMIT() asm volatile("cp.async.commit_group;\n" ::: "memory")
__device__ __forceinline__ void ldsm4(uint32_t& r0, uint32_t& r1, uint32_t& r2, uint32_t& r3,
                                      const void* p) {
    uint32_t a = (uint32_t)__cvta_generic_to_shared(p);
    asm volatile("ldmatrix.sync.aligned.m8n8.x4.shared.b16 {%0,%1,%2,%3}, [%4];\n"
                 : "=r"(r0), "=r"(r1), "=r"(r2), "=r"(r3) : "r"(a));
}
__device__ __forceinline__ void ldsm4t(uint32_t& r0, uint32_t& r1, uint32_t& r2, uint32_t& r3,
                                       const void* p) {
    uint32_t a = (uint32_t)__cvta_generic_to_shared(p);
    asm volatile("ldmatrix.sync.aligned.m8n8.x4.trans.shared.b16 {%0,%1,%2,%3}, [%4];\n"
                 : "=r"(r0), "=r"(r1), "=r"(r2), "=r"(r3) : "r"(a));
}
__device__ __forceinline__ void mma_bf16(float c[4], const uint32_t a[4], const uint32_t b[2]) {
    asm volatile(
        "mma.sync.aligned.m16n8k16.row.col.f32.bf16.bf16.f32 "
        "{%0,%1,%2,%3}, {%4,%5,%6,%7}, {%8,%9}, {%0,%1,%2,%3};\n"
        : "+f"(c[0]), "+f"(c[1]), "+f"(c[2]), "+f"(c[3])
        : "r"(a[0]), "r"(a[1]), "r"(a[2]), "r"(a[3]), "r"(b[0]), "r"(b[1]));
}

// ---------------- split f32 -> bf16 hi/lo ----------------
__global__ void splitk(const float* __restrict__ src, __nv_bfloat16* __restrict__ hi,
                       __nv_bfloat16* __restrict__ lo, int n) {
    int i = blockIdx.x*blockDim.x + threadIdx.x;
    if (i >= n) return;
    float v = src[i];
    __nv_bfloat16 h = __float2bfloat16(v);
    hi[i] = h;
    lo[i] = __float2bfloat16(v - __bfloat162float(h));
}

// ---------------- embedding + PE ----------------
__global__ void embed_enc(const int* __restrict__ x, const float* __restrict__ emb,
                          float* __restrict__ e, __nv_bfloat16* __restrict__ ehi,
                          __nv_bfloat16* __restrict__ elo) {
    int idx = blockIdx.x*blockDim.x + threadIdx.x;
    if (idx >= Bz*Sz*Dm) return;
    int d  = idx % Dm;
    int bs = idx / Dm;
    int s  = bs % Sz;
    int tok = x[bs];
    float div = exp2f(-(float)(d & ~1) * (13.287712379549449f / (float)Dm));
    float arg = (float)s * div;
    float pe = (d & 1) ? cosf(arg) : sinf(arg);
    float v = emb[tok*Dm + d] * 22.627416997969522f + pe;
    e[idx] = v;
    __nv_bfloat16 h = __float2bfloat16(v);
    ehi[idx] = h;
    elo[idx] = __float2bfloat16(v - __bfloat162float(h));
}

__global__ void embed_dec(const int* __restrict__ tgt, const float* __restrict__ emb,
                          float* __restrict__ o) {
    int idx = blockIdx.x*blockDim.x + threadIdx.x;
    if (idx >= Bz*Dm) return;
    int d = idx % Dm;
    int b = idx / Dm;
    float pe = (d & 1) ? 1.f : 0.f;
    o[idx] = emb[tgt[b]*Dm + d] * 22.627416997969522f + pe;
}

// ============ 3-stage pipelined mma.sync GEMM (bf16x3, big tiles) ===========
// C[M,N] = A[M,K] @ B[K,N]; A as bf16 hi/lo [M,K]. B [K,N] (ldmatrix.trans).
// BM=128; BN_=128 -> 256 thr (2m x 4n); BN_=64 -> 128 thr (2m x 2n).
// EPI: 0=+bias, 1=+bias+relu, 3=none.  WMODE bit0: f32 C; bit1: split planes.
template<int BN_, int EPI, int WMODE>
__global__ void __launch_bounds__(BN_ == 128 ? 256 : 128, 1)
gemm_mma(const __nv_bfloat16* __restrict__ Agh, const __nv_bfloat16* __restrict__ Agl,
         const __nv_bfloat16* __restrict__ Bgh, const __nv_bfloat16* __restrict__ Bgl,
         const float* __restrict__ bias,
         float* __restrict__ C, __nv_bfloat16* __restrict__ Chi,
         __nv_bfloat16* __restrict__ Clo,
         int K, int lda, int ldb, int ldc,
         int zdiv, long long sA1, long long sA2, long long sB1, long long sB2,
         long long sC1, long long sC2, long long sBias) {
    constexpr int NT   = (BN_ == 128) ? 256 : 128;
    constexpr int ASTG = 128 * 40;
    constexpr int BLD  = BN_ + 8;
    constexpr int BSTG = 32 * BLD;

    extern __shared__ __nv_bfloat16 sm[];
    __nv_bfloat16* Ah = sm;
    __nv_bfloat16* Al = Ah + 3*ASTG;
    __nv_bfloat16* Bh = Al + 3*ASTG;
    __nv_bfloat16* Bl = Bh + 3*BSTG;

    int z = blockIdx.z, z1 = z / zdiv, z2 = z % zdiv;
    const __nv_bfloat16* Abh = Agh + z1*sA1 + z2*sA2;
    const __nv_bfloat16* Abl = Agl + z1*sA1 + z2*sA2;
    const __nv_bfloat16* Bbh = Bgh + z1*sB1 + z2*sB2;
    const __nv_bfloat16* Bbl = Bgl + z1*sB1 + z2*sB2;
    long long coff = z1*sC1 + z2*sC2;

    int m0 = blockIdx.y * 128, n0 = blockIdx.x * BN_;
    int tid = threadIdx.x, lane = tid & 31, wid = tid >> 5;
    int wm = wid & 1, wn = wid >> 1;
    int gid = lane >> 2, tig = lane & 3;

    auto load_stage = [&](int st, int kt) {
        int k0 = kt * 32;
        for (int idx = tid; idx < 512; idx += NT) {
            int r = idx >> 2, c = (idx & 3) * 8;
            int so = st*ASTG + r*40 + c;
            cpa16(Ah + so, Abh + (size_t)(m0 + r)*lda + k0 + c);
            cpa16(Al + so, Abl + (size_t)(m0 + r)*lda + k0 + c);
        }
        constexpr int CH = BN_ / 8;
        for (int idx = tid; idx < 32*CH; idx += NT) {
            int r = idx / CH, c = (idx % CH) * 8;
            int so = st*BSTG + r*BLD + c;
            cpa16(Bh + so, Bbh + (size_t)(k0 + r)*ldb + n0 + c);
            cpa16(Bl + so, Bbl + (size_t)(k0 + r)*ldb + n0 + c);
        }
    };

    float acc[4][4][4] = {};
    const int KT = K >> 5;

    load_stage(0, 0); CP_COMMIT();
    if (KT > 1) { load_stage(1, 1); CP_COMMIT(); }
    if (KT > 1) asm volatile("cp.async.wait_group 1;\n" ::: "memory");
    else        asm volatile("cp.async.wait_group 0;\n" ::: "memory");
    __syncthreads();

    for (int c = 0; c < KT; c++) {
        int st = c % 3;
        const __nv_bfloat16* a_h = Ah + st*ASTG;
        const __nv_bfloat16* a_l = Al + st*ASTG;
        const __nv_bfloat16* b_h = Bh + st*BSTG;
        const __nv_bfloat16* b_l = Bl + st*BSTG;

#pragma unroll
        for (int kk = 0; kk < 2; kk++) {
            int kc = kk*16 + ((lane >> 4) << 3);
            uint32_t ah[4][4], al[4][4], bh[4][2], bl[4][2];
#pragma unroll
            for (int mi = 0; mi < 4; mi++) {
                int ar = wm*64 + mi*16 + (lane & 15);
                ldsm4(ah[mi][0], ah[mi][1], ah[mi][2], ah[mi][3], a_h + ar*40 + kc);
                ldsm4(al[mi][0], al[mi][1], al[mi][2], al[mi][3], a_l + ar*40 + kc);
            }
#pragma unroll
            for (int ng = 0; ng < 2; ng++) {
                uint32_t r0, r1, r2, r3;
                int rr = kk*16 + ((lane >> 4) << 3) + (lane & 7);
                int cc = wn*32 + ng*16 + (((lane >> 3) & 1) << 3);
                ldsm4t(r0, r1, r2, r3, b_h + rr*BLD + cc);
                bh[ng*2  ][0] = r0; bh[ng*2  ][1] = r2;
                bh[ng*2+1][0] = r1; bh[ng*2+1][1] = r3;
                ldsm4t(r0, r1, r2, r3, b_l + rr*BLD + cc);
                bl[ng*2  ][0] = r0; bl[ng*2  ][1] = r2;
                bl[ng*2+1][0] = r1; bl[ng*2+1][1] = r3;
            }
#pragma unroll
            for (int mi = 0; mi < 4; mi++)
#pragma unroll
                for (int ni = 0; ni < 4; ni++) mma_bf16(acc[mi][ni], ah[mi], bh[ni]);
#pragma unroll
            for (int mi = 0; mi < 4; mi++)
#pragma unroll
                for (int ni = 0; ni < 4; ni++) mma_bf16(acc[mi][ni], ah[mi], bl[ni]);
#pragma unroll
            for (int mi = 0; mi < 4; mi++)
#pragma unroll
                for (int ni = 0; ni < 4; ni++) mma_bf16(acc[mi][ni], al[mi], bh[ni]);
        }

        if (c + 2 < KT) {
            load_stage((c + 2) % 3, c + 2);
            CP_COMMIT();
            asm volatile("cp.async.wait_group 1;\n" ::: "memory");
            __syncthreads();
        } else if (c + 1 < KT) {
            asm volatile("cp.async.wait_group 0;\n" ::: "memory");
            __syncthreads();
        }
    }

    const float* biasb = (EPI <= 1) ? bias + (long long)z * sBias : nullptr;
#pragma unroll
    for (int mi = 0; mi < 4; mi++)
#pragma unroll
        for (int ni = 0; ni < 4; ni++) {
            int row = m0 + wm*64 + mi*16 + gid;
            int col = n0 + wn*32 + ni*8 + tig*2;
#pragma unroll
            for (int e2 = 0; e2 < 4; e2++) {
                int r  = row + (e2 >> 1)*8;
                int cc = col + (e2 & 1);
                float v = acc[mi][ni][e2];
                if (EPI == 0 || EPI == 1) v += biasb[cc];
                if (EPI == 1) v = fmaxf(v, 0.f);
                size_t idx = (size_t)(coff + (long long)r*ldc + cc);
                if (WMODE & 1) C[idx] = v;
                if (WMODE & 2) {
                    __nv_bfloat16 h = __float2bfloat16(v);
                    Chi[idx] = h;
                    Clo[idx] = __float2bfloat16(v - __bfloat162float(h));
                }
            }
        }
}

// ============ fused scores + mask + softmax + split =========================
// Per (b,h): S = Q K^T / 8, (==0 -> NEGV), row softmax, write split planes.
// CTA: 64 q-rows x full 512 k-cols, K=64 single shot. 256 thr, warps 2m x 4n.
__global__ void __launch_bounds__(256)
scores_softmax(const __nv_bfloat16* __restrict__ qh, const __nv_bfloat16* __restrict__ ql,
               const __nv_bfloat16* __restrict__ kh, const __nv_bfloat16* __restrict__ kl,
               __nv_bfloat16* __restrict__ phi, __nv_bfloat16* __restrict__ plo) {
    extern __shared__ __nv_bfloat16 sm[];
    __nv_bfloat16* Qh = sm;                 // 64*72
    __nv_bfloat16* Ql = Qh + 64*72;
    __nv_bfloat16* Kh = Ql + 64*72;         // 512*72
    __nv_bfloat16* Kl = Kh + 512*72;

    int bh = blockIdx.y, b = bh >> 3, h = bh & 7;
    int q0 = blockIdx.x * 64;
    int tid = threadIdx.x, lane = tid & 31, wid = tid >> 5;
    int wm = wid & 1, wn = wid >> 1;
    int gid = lane >> 2, tig = lane & 3;

    for (int idx = tid; idx < 512; idx += 256) {
        int r = idx >> 3, c = (idx & 7) * 8;
        size_t go = (size_t)(b*Sz + q0 + r)*Dm + h*DKh + c;
        cpa16(Qh + r*72 + c, qh + go);
        cpa16(Ql + r*72 + c, ql + go);
    }
    for (int idx = tid; idx < 4096; idx += 256) {
        int r = idx >> 3, c = (idx & 7) * 8;
        size_t go = (size_t)(b*Sz + r)*Dm + h*DKh + c;
        cpa16(Kh + r*72 + c, kh + go);
        cpa16(Kl + r*72 + c, kl + go);
    }
    CP_COMMIT();
    asm volatile("cp.async.wait_group 0;\n" ::: "memory");
    __syncthreads();

    float acc[2][16][4] = {};
#pragma unroll
    for (int kk = 0; kk < 4; kk++) {
        int kc = kk*16 + ((lane >> 4) << 3);
        uint32_t ah[2][4], al[2][4];
#pragma unroll
        for (int mi = 0; mi < 2; mi++) {
            int ar = wm*32 + mi*16 + (lane & 15);
            ldsm4(ah[mi][0], ah[mi][1], ah[mi][2], ah[mi][3], Qh + ar*72 + kc);
            ldsm4(al[mi][0], al[mi][1], al[mi][2], al[mi][3], Ql + ar*72 + kc);
        }
#pragma unroll
        for (int ng = 0; ng < 8; ng++) {
            int br = wn*128 + ng*16 + (lane & 15);
            uint32_t r0, r1, r2, r3;
            uint32_t bhf[2][2], blf[2][2];
            ldsm4(r0, r1, r2, r3, Kh + br*72 + kc);
            bhf[0][0] = r0; bhf[0][1] = r2; bhf[1][0] = r1; bhf[1][1] = r3;
            ldsm4(r0, r1, r2, r3, Kl + br*72 + kc);
            blf[0][0] = r0; blf[0][1] = r2; blf[1][0] = r1; blf[1][1] = r3;
#pragma unroll
            for (int mi = 0; mi < 2; mi++)
#pragma unroll
                for (int sub = 0; sub < 2; sub++) {
                    mma_bf16(acc[mi][ng*2+sub], ah[mi], bhf[sub]);
                    mma_bf16(acc[mi][ng*2+sub], ah[mi], blf[sub]);
                    mma_bf16(acc[mi][ng*2+sub], al[mi], bhf[sub]);
                }
        }
    }
    __syncthreads();                 // smem reuse below
    float* rmax = (float*)sm;        // [64][4]
    float* rsum = rmax + 256;        // [64][4]

    // mask + scale, per-row max (tig shuffle + cross-warp smem)
#pragma unroll
    for (int mi = 0; mi < 2; mi++)
#pragma unroll
        for (int rh = 0; rh < 2; rh++) {
            float m1 = -INFINITY;
#pragma unroll
            for (int ni = 0; ni < 16; ni++)
#pragma unroll
                for (int nj = 0; nj < 2; nj++) {
                    float v = acc[mi][ni][rh*2+nj] * 0.125f;
                    if (v == 0.f) v = NEGV;
                    acc[mi][ni][rh*2+nj] = v;
                    m1 = fmaxf(m1, v);
                }
            m1 = fmaxf(m1, __shfl_xor_sync(0xffffffffu, m1, 1));
            m1 = fmaxf(m1, __shfl_xor_sync(0xffffffffu, m1, 2));
            int row = wm*32 + mi*16 + rh*8 + gid;
            if (tig == 0) rmax[row*4 + wn] = m1;
        }
    __syncthreads();
#pragma unroll
    for (int mi = 0; mi < 2; mi++)
#pragma unroll
        for (int rh = 0; rh < 2; rh++) {
            int row = wm*32 + mi*16 + rh*8 + gid;
            float mx = fmaxf(fmaxf(rmax[row*4+0], rmax[row*4+1]),
                             fmaxf(rmax[row*4+2], rmax[row*4+3]));
            float s1 = 0.f;
#pragma unroll
            for (int ni = 0; ni < 16; ni++)
#pragma unroll
                for (int nj = 0; nj < 2; nj++) {
                    float v = expf(acc[mi][ni][rh*2+nj] - mx);
                    acc[mi][ni][rh*2+nj] = v;
                    s1 += v;
                }
            s1 += __shfl_xor_sync(0xffffffffu, s1, 1);
            s1 += __shfl_xor_sync(0xffffffffu, s1, 2);
            if (tig == 0) rsum[row*4 + wn] = s1;
        }
    __syncthreads();
#pragma unroll
    for (int mi = 0; mi < 2; mi++)
#pragma unroll
        for (int rh = 0; rh < 2; rh++) {
            int row = wm*32 + mi*16 + rh*8 + gid;
            float inv = 1.f / (rsum[row*4+0] + rsum[row*4+1] + rsum[row*4+2] + rsum[row*4+3]);
            size_t base = ((size_t)bh*Sz + q0 + row)*Sz;
#pragma unroll
            for (int ni = 0; ni < 16; ni++) {
                int col = wn*128 + (ni>>1)*16 + (ni&1)*8 + tig*2;
                float v0 = acc[mi][ni][rh*2+0] * inv;
                float v1 = acc[mi][ni][rh*2+1] * inv;
                __nv_bfloat16 h0 = __float2bfloat16(v0);
                __nv_bfloat16 h1 = __float2bfloat16(v1);
                __nv_bfloat16 l0 = __float2bfloat16(v0 - __bfloat162float(h0));
                __nv_bfloat16 l1 = __float2bfloat16(v1 - __bfloat162float(h1));
                uint32_t ph = ((uint32_t)*(uint16_t*)&h1 << 16) | *(uint16_t*)&h0;
                uint32_t pl = ((uint32_t)*(uint16_t*)&l1 << 16) | *(uint16_t*)&l0;
                *(uint32_t*)(phi + base + col) = ph;
                *(uint32_t*)(plo + base + col) = pl;
            }
        }
}

// ---------------- out = LayerNorm(a + res) (+ optional split) ---------------
template<int SPLIT>
__global__ void add_ln(const float* __restrict__ a, const float* __restrict__ res,
                       const float* __restrict__ g, const float* __restrict__ beta,
                       float* __restrict__ out, __nv_bfloat16* __restrict__ ohi,
                       __nv_bfloat16* __restrict__ olo) {
    size_t row = blockIdx.x;
    int tid = threadIdx.x;
    int c = tid * 4;
    float4 av = *(const float4*)&a[row*Dm + c];
    float4 rv = *(const float4*)&res[row*Dm + c];
    float4 x;
    x.x = av.x + rv.x; x.y = av.y + rv.y; x.z = av.z + rv.z; x.w = av.w + rv.w;
    float s  = x.x + x.y + x.z + x.w;
    float s2 = x.x*x.x + x.y*x.y + x.z*x.z + x.w*x.w;
#pragma unroll
    for (int o = 16; o; o >>= 1) {
        s  += __shfl_xor_sync(0xffffffffu, s,  o);
        s2 += __shfl_xor_sync(0xffffffffu, s2, o);
    }
    __shared__ float sm[4], sq[4];
    if ((tid & 31) == 0) { sm[tid>>5] = s; sq[tid>>5] = s2; }
    __syncthreads();
    s  = sm[0] + sm[1] + sm[2] + sm[3];
    s2 = sq[0] + sq[1] + sq[2] + sq[3];
    float mean = s * (1.f/Dm);
    float var  = s2 * (1.f/Dm) - mean*mean;
    float inv  = rsqrtf(var + 1e-5f);
    float4 gv = *(const float4*)&g[c];
    float4 bv = *(const float4*)&beta[c];
    float y[4];
    y[0] = (x.x - mean)*inv*gv.x + bv.x;
    y[1] = (x.y - mean)*inv*gv.y + bv.y;
    y[2] = (x.z - mean)*inv*gv.z + bv.z;
    y[3] = (x.w - mean)*inv*gv.w + bv.w;
    *(float4*)&out[row*Dm + c] = *(float4*)y;
    if (SPLIT) {
        __nv_bfloat16 hh[4], ll[4];
#pragma unroll
        for (int j = 0; j < 4; j++) {
            hh[j] = __float2bfloat16(y[j]);
            ll[j] = __float2bfloat16(y[j] - __bfloat162float(hh[j]));
        }
        *(uint2*)&ohi[row*Dm + c] = *(uint2*)hh;
        *(uint2*)&olo[row*Dm + c] = *(uint2*)ll;
    }
}

// ---------------- decoder cross-attention (Sq=1, f32) ----------------
__global__ void cross_attn(const float* __restrict__ q, const float* __restrict__ k,
                           const float* __restrict__ v, float* __restrict__ o) {
    int h = blockIdx.x, b = blockIdx.y;
    __shared__ float qv[64];
    __shared__ float p[512];
    __shared__ float red[8];
    int tid = threadIdx.x;
    if (tid < 64) qv[tid] = q[b*Dm + h*DKh + tid];
    __syncthreads();
    float sc[2];
    float lmax = -INFINITY;
#pragma unroll
    for (int it = 0; it < 2; it++) {
        int j = tid + it*256;
        const float* kp = &k[(size_t)(b*Sz + j)*Dm + h*DKh];
        float s = 0.f;
#pragma unroll
        for (int c = 0; c < 64; c++) s += qv[c] * kp[c];
        s *= 0.125f;
        if (s == 0.f) s = NEGV;
        sc[it] = s;
        lmax = fmaxf(lmax, s);
    }
#pragma unroll
    for (int off = 16; off; off >>= 1) lmax = fmaxf(lmax, __shfl_xor_sync(0xffffffffu, lmax, off));
    if ((tid & 31) == 0) red[tid >> 5] = lmax;
    __syncthreads();
    float mx = red[0];
#pragma unroll
    for (int w = 1; w < 8; w++) mx = fmaxf(mx, red[w]);
    __syncthreads();
    float lsum = 0.f;
#pragma unroll
    for (int it = 0; it < 2; it++) {
        float e = expf(sc[it] - mx);
        p[tid + it*256] = e;
        lsum += e;
    }
#pragma unroll
    for (int off = 16; off; off >>= 1) lsum += __shfl_xor_sync(0xffffffffu, lsum, off);
    if ((tid & 31) == 0) red[tid >> 5] = lsum;
    __syncthreads();
    float sum = red[0] + red[1] + red[2] + red[3] + red[4] + red[5] + red[6] + red[7];
    float inv = 1.f / sum;
    int warp = tid >> 5, lane = tid & 31;
#pragma unroll
    for (int dd = 0; dd < 8; dd++) {
        int d = warp*8 + dd;
        float acc = 0.f;
        for (int j = lane; j < Sz; j += 32)
            acc += p[j] * v[(size_t)(b*Sz + j)*Dm + h*DKh + d];
#pragma unroll
        for (int off = 16; off; off >>= 1) acc += __shfl_xor_sync(0xffffffffu, acc, off);
        if (lane == 0) o[b*Dm + h*DKh + d] = acc * inv;
    }
}

// ---------- tiny-M (M=8) GEMM, K-parallel: 512 thr = 64 cols x 8 K-slices ---
template<int RELU>
__global__ void __launch_bounds__(512)
gemm8w(const float* __restrict__ A, const float* __restrict__ W,
       const float* __restrict__ bias, float* __restrict__ C, int K, int N) {
    __shared__ float red[8][8][64];   // [row][slice][col]
    int t = threadIdx.x;
    int cl = t & 63;
    int col = blockIdx.x*64 + cl;
    int sl = t >> 6;                  // 0..7
    float acc[8] = {};
    if (col < N) {
        int kn = K >> 3;
        int k0 = sl * kn, k1 = k0 + kn;
        for (int k = k0; k < k1; k++) {
            float wv = W[(size_t)k*N + col];
#pragma unroll
            for (int r = 0; r < 8; r++) acc[r] += A[r*K + k] * wv;
        }
    }
#pragma unroll
    for (int r = 0; r < 8; r++) red[r][sl][cl] = acc[r];
    __syncthreads();
    if (t < 64 && col < N) {
        float bv = bias[col];
#pragma unroll
        for (int r = 0; r < 8; r++) {
            float s = 0.f;
#pragma unroll
            for (int s8 = 0; s8 < 8; s8++) s += red[r][s8][t];
            float val = s + bv;
            if (RELU) val = fmaxf(val, 0.f);
            C[r*N + col] = val;
        }
    }
}

// ---------------- host orchestration ----------------
extern "C" void kernel_launch(void* const* d_in, const int* in_sizes, int n_in,
                              void* d_out, int out_size) {
    const int*   x        = (const int*)d_in[0];
    const int*   tgt      = (const int*)d_in[1];
    const float* in_emb   = (const float*)d_in[2];
    const float* out_emb  = (const float*)d_in[3];
    const float* enc_qkv_w = (const float*)d_in[4];
    const float* enc_qkv_b = (const float*)d_in[5];
    const float* enc_ln1_g = (const float*)d_in[6];
    const float* enc_ln1_b = (const float*)d_in[7];
    const float* enc_ffn1_w = (const float*)d_in[8];
    const float* enc_ffn1_b = (const float*)d_in[9];
    const float* enc_ffn2_w = (const float*)d_in[10];
    const float* enc_ffn2_b = (const float*)d_in[11];
    const float* enc_ln2_g = (const float*)d_in[12];
    const float* enc_ln2_b = (const float*)d_in[13];
    const float* dec_qkv1_w = (const float*)d_in[14];
    const float* dec_qkv1_b = (const float*)d_in[15];
    const float* dec_ln1_g = (const float*)d_in[16];
    const float* dec_ln1_b = (const float*)d_in[17];
    const float* dec_qkv2_w = (const float*)d_in[18];
    const float* dec_qkv2_b = (const float*)d_in[19];
    const float* dec_ln2_g = (const float*)d_in[20];
    const float* dec_ln2_b = (const float*)d_in[21];
    const float* dec_ffn1_w = (const float*)d_in[22];
    const float* dec_ffn1_b = (const float*)d_in[23];
    const float* dec_ffn2_w = (const float*)d_in[24];
    const float* dec_ffn2_b = (const float*)d_in[25];
    const float* dec_ln3_g = (const float*)d_in[26];
    const float* dec_ln3_b = (const float*)d_in[27];
    const float* out_w = (const float*)d_in[28];
    const float* out_b = (const float*)d_in[29];

    float *e, *attn, *tbuf, *dbuf, *dq, *dt, *dh, *kvf;
    __nv_bfloat16 *ehi, *elo, *qkvh, *qkvl, *schi, *sclo, *hhi, *hlo;
    __nv_bfloat16 *wqkvh, *wqkvl, *wf1h, *wf1l, *wf2h, *wf2l, *wd2h, *wd2l;
    cudaGetSymbolAddress((void**)&e,    g_e);
    cudaGetSymbolAddress((void**)&ehi,  g_ehi);
    cudaGetSymbolAddress((void**)&elo,  g_elo);
    cudaGetSymbolAddress((void**)&qkvh, g_qkvh);
    cudaGetSymbolAddress((void**)&qkvl, g_qkvl);
    cudaGetSymbolAddress((void**)&kvf,  g_kvf);
    cudaGetSymbolAddress((void**)&schi, g_schi);
    cudaGetSymbolAddress((void**)&sclo, g_sclo);
    cudaGetSymbolAddress((void**)&attn, g_attn);
    cudaGetSymbolAddress((void**)&hhi,  g_hhi);
    cudaGetSymbolAddress((void**)&hlo,  g_hlo);
    cudaGetSymbolAddress((void**)&tbuf, g_t);
    cudaGetSymbolAddress((void**)&dbuf, g_d);
    cudaGetSymbolAddress((void**)&dq,   g_dq);
    cudaGetSymbolAddress((void**)&dt,   g_dt);
    cudaGetSymbolAddress((void**)&dh,   g_dh);
    cudaGetSymbolAddress((void**)&wqkvh, g_wqkvh);
    cudaGetSymbolAddress((void**)&wqkvl, g_wqkvl);
    cudaGetSymbolAddress((void**)&wf1h, g_wf1h);
    cudaGetSymbolAddress((void**)&wf1l, g_wf1l);
    cudaGetSymbolAddress((void**)&wf2h, g_wf2h);
    cudaGetSymbolAddress((void**)&wf2l, g_wf2l);
    cudaGetSymbolAddress((void**)&wd2h, g_wd2h);
    cudaGetSymbolAddress((void**)&wd2l, g_wd2l);

    const int M = Bz*Sz;            // 4096
    const long long DD = (long long)Dm*Dm;
    const long long MD = (long long)M*Dm;
    const long long SS = (long long)Sz*Sz;
    const long long SDm = (long long)Sz*Dm;

    const int SM_TB0_128 = 61440 + 2*3*32*136*2;   // 113664
    const int SM_TB0_64  = 61440 + 2*3*32*72*2;    //  89088
    const int SM_SCORES  = (64*72*2 + 512*72*2) * 2;  // 165888
    cudaFuncSetAttribute(gemm_mma<128,0,2>, cudaFuncAttributeMaxDynamicSharedMemorySize, SM_TB0_128);
    cudaFuncSetAttribute(gemm_mma<64,3,1>,  cudaFuncAttributeMaxDynamicSharedMemorySize, SM_TB0_64);
    cudaFuncSetAttribute(gemm_mma<128,1,2>, cudaFuncAttributeMaxDynamicSharedMemorySize, SM_TB0_128);
    cudaFuncSetAttribute(gemm_mma<128,0,1>, cudaFuncAttributeMaxDynamicSharedMemorySize, SM_TB0_128);
    cudaFuncSetAttribute(scores_softmax,    cudaFuncAttributeMaxDynamicSharedMemorySize, SM_SCORES);

    // ---- split weights once per launch ----
    {
        int n1 = Lz*3*Dm*Dm;
        splitk<<<(n1+255)/256, 256>>>(enc_qkv_w, wqkvh, wqkvl, n1);
        int n2 = Lz*Dm*DFFz;
        splitk<<<(n2+255)/256, 256>>>(enc_ffn1_w, wf1h, wf1l, n2);
        splitk<<<(n2+255)/256, 256>>>(enc_ffn2_w, wf2h, wf2l, n2);
        splitk<<<(n1+255)/256, 256>>>(dec_qkv2_w, wd2h, wd2l, n1);
    }

    // ---------------- encoder ----------------
    embed_enc<<<(Bz*Sz*Dm + 255)/256, 256>>>(x, in_emb, e, ehi, elo);
    for (int i = 0; i < Lz; i++) {
        gemm_mma<128,0,2><<<dim3(Dm/128, M/128, 3), 256, SM_TB0_128>>>(
            ehi, elo, wqkvh + (size_t)i*3*DD, wqkvl + (size_t)i*3*DD,
            enc_qkv_b + (size_t)i*3*Dm, nullptr, qkvh, qkvl,
            Dm, Dm, Dm, Dm,
            1, 0, 0, DD, 0, MD, 0, Dm);
        scores_softmax<<<dim3(Sz/64, Bz*Hn), 256, SM_SCORES>>>(
            qkvh, qkvl, qkvh + MD, qkvl + MD, schi, sclo);
        gemm_mma<64,3,1><<<dim3(1, Sz/128, Bz*Hn), 128, SM_TB0_64>>>(
            schi, sclo, qkvh + 2*MD, qkvl + 2*MD, nullptr, attn, nullptr, nullptr,
            Sz, Sz, Dm, Dm,
            Hn, (long long)Hn*SS, SS, SDm, DKh, SDm, DKh, 0);
        add_ln<1><<<M, 128>>>(attn, e, enc_ln1_g + i*Dm, enc_ln1_b + i*Dm, e, ehi, elo);
        gemm_mma<128,1,2><<<dim3(DFFz/128, M/128, 1), 256, SM_TB0_128>>>(
            ehi, elo, wf1h + (size_t)i*Dm*DFFz, wf1l + (size_t)i*Dm*DFFz,
            enc_ffn1_b + (size_t)i*DFFz, nullptr, hhi, hlo,
            Dm, Dm, DFFz, DFFz,
            1, 0, 0, 0, 0, 0, 0, 0);
        gemm_mma<128,0,1><<<dim3(Dm/128, M/128, 1), 256, SM_TB0_128>>>(
            hhi, hlo, wf2h + (size_t)i*DFFz*Dm, wf2l + (size_t)i*DFFz*Dm,
            enc_ffn2_b + (size_t)i*Dm, tbuf, nullptr, nullptr,
            DFFz, DFFz, Dm, Dm,
            1, 0, 0, 0, 0, 0, 0, 0);
        add_ln<1><<<M, 128>>>(tbuf, e, enc_ln2_g + i*Dm, enc_ln2_b + i*Dm, e, ehi, elo);
    }

    // ---------------- decoder (seq len 1; self-attn == V projection) --------
    embed_dec<<<(Bz*Dm + 255)/256, 256>>>(tgt, out_emb, dbuf);
    for (int i = 0; i < Lz; i++) {
        gemm8w<0><<<Dm/64, 512>>>(dbuf, dec_qkv1_w + (size_t)(i*3+2)*DD, dec_qkv1_b + (i*3+2)*Dm, dt, Dm, Dm);
        add_ln<0><<<Bz, 128>>>(dt, dbuf, dec_ln1_g + i*Dm, dec_ln1_b + i*Dm, dbuf, nullptr, nullptr);
        gemm8w<0><<<Dm/64, 512>>>(dbuf, dec_qkv2_w + (size_t)(i*3+0)*DD, dec_qkv2_b + (i*3+0)*Dm, dq, Dm, Dm);
        gemm_mma<128,0,1><<<dim3(Dm/128, M/128, 2), 256, SM_TB0_128>>>(
            ehi, elo, wd2h + (size_t)(i*3+1)*DD, wd2l + (size_t)(i*3+1)*DD,
            dec_qkv2_b + (size_t)(i*3+1)*Dm, kvf, nullptr, nullptr,
            Dm, Dm, Dm, Dm,
            1, 0, 0, DD, 0, MD, 0, Dm);
        cross_attn<<<dim3(Hn, Bz), 256>>>(dq, kvf /*K*/, kvf + MD /*V*/, dt);
        add_ln<0><<<Bz, 128>>>(dt, dbuf, dec_ln2_g + i*Dm, dec_ln2_b + i*Dm, dbuf, nullptr, nullptr);
        gemm8w<1><<<DFFz/64, 512>>>(dbuf, dec_ffn1_w + (size_t)i*Dm*DFFz, dec_ffn1_b + i*DFFz, dh, Dm, DFFz);
        gemm8w<0><<<Dm/64, 512>>>(dh, dec_ffn2_w + (size_t)i*DFFz*Dm, dec_ffn2_b + i*Dm, dt, DFFz, Dm);
        add_ln<0><<<Bz, 128>>>(dt, dbuf, dec_ln3_g + i*Dm, dec_ln3_b + i*Dm, dbuf, nullptr, nullptr);
    }

    // output projection -> d_out [8,1,1000]
    gemm8w<0><<<(OUTz+63)/64, 512>>>(dbuf, out_w, out_b, (float*)d_out, Dm, OUTz);
    (void)in_sizes; (void)n_in; (void)out_size;
}

// round 8
// speedup vs baseline: 2.2254x; 1.0114x over previous
#include <cuda_runtime.h>
#include <cuda_bf16.h>
#include <math.h>
#include <stdint.h>

#define Bz   8
#define Sz   512
#define Dm   512
#define Hn   8
#define DKh  64
#define Lz   6
#define DFFz 2048
#define OUTz 1000
#define NEGV (-1e9f)

// ---------------- scratch (device globals) ----------------
__device__ float g_e[Bz*Sz*Dm];
__device__ __nv_bfloat16 g_ehi[Bz*Sz*Dm], g_elo[Bz*Sz*Dm];
__device__ __nv_bfloat16 g_qkvh[3*Bz*Sz*Dm], g_qkvl[3*Bz*Sz*Dm];
__device__ float g_kvf[(size_t)Lz*2*Bz*Sz*Dm];
__device__ __nv_bfloat16 g_schi[(size_t)Bz*Hn*Sz*Sz], g_sclo[(size_t)Bz*Hn*Sz*Sz];
__device__ float g_attn[Bz*Sz*Dm];
__device__ __nv_bfloat16 g_hhi[Bz*Sz*DFFz], g_hlo[Bz*Sz*DFFz];
__device__ float g_t[Bz*Sz*Dm];
__device__ float g_d[Bz*Dm];
__device__ float g_dq[Bz*Dm];
__device__ float g_dt[Bz*Dm];
__device__ float g_dh[Bz*DFFz];
// split weights in original [K,N] layout
__device__ __nv_bfloat16 g_wqkvh[Lz*3*Dm*Dm], g_wqkvl[Lz*3*Dm*Dm];
__device__ __nv_bfloat16 g_wf1h[Lz*Dm*DFFz],  g_wf1l[Lz*Dm*DFFz];
__device__ __nv_bfloat16 g_wf2h[Lz*DFFz*Dm],  g_wf2l[Lz*DFFz*Dm];
__device__ __nv_bfloat16 g_wd2h[Lz*3*Dm*Dm],  g_wd2l[Lz*3*Dm*Dm];

// ---------------- helpers ----------------
__device__ __forceinline__ void cpa16(void* dst, const void* src) {
    uint32_t d = (uint32_t)__cvta_generic_to_shared(dst);
    asm volatile("cp.async.ca.shared.global [%0], [%1], 16;\n" :: "r"(d), "l"(src));
}
#define CP_COMMIT() asm volatile("cp.async.commit_group;\n" ::: "memory")
__device__ __forceinline__ void ldsm4(uint32_t& r0, uint32_t& r1, uint32_t& r2, uint32_t& r3,
                                      const void* p) {
    uint32_t a = (uint32_t)__cvta_generic_to_shared(p);
    asm volatile("ldmatrix.sync.aligned.m8n8.x4.shared.b16 {%0,%1,%2,%3}, [%4];\n"
                 : "=r"(r0), "=r"(r1), "=r"(r2), "=r"(r3) : "r"(a));
}
__device__ __forceinline__ void ldsm4t(uint32_t& r0, uint32_t& r1, uint32_t& r2, uint32_t& r3,
                                       const void* p) {
    uint32_t a = (uint32_t)__cvta_generic_to_shared(p);
    asm volatile("ldmatrix.sync.aligned.m8n8.x4.trans.shared.b16 {%0,%1,%2,%3}, [%4];\n"
                 : "=r"(r0), "=r"(r1), "=r"(r2), "=r"(r3) : "r"(a));
}
__device__ __forceinline__ void mma_bf16(float c[4], const uint32_t a[4], const uint32_t b[2]) {
    asm volatile(
        "mma.sync.aligned.m16n8k16.row.col.f32.bf16.bf16.f32 "
        "{%0,%1,%2,%3}, {%4,%5,%6,%7}, {%8,%9}, {%0,%1,%2,%3};\n"
        : "+f"(c[0]), "+f"(c[1]), "+f"(c[2]), "+f"(c[3])
        : "r"(a[0]), "r"(a[1]), "r"(a[2]), "r"(a[3]), "r"(b[0]), "r"(b[1]));
}

// ---------------- split f32 -> bf16 hi/lo ----------------
__global__ void splitk(const float* __restrict__ src, __nv_bfloat16* __restrict__ hi,
                       __nv_bfloat16* __restrict__ lo, int n) {
    int i = blockIdx.x*blockDim.x + threadIdx.x;
    if (i >= n) return;
    float v = src[i];
    __nv_bfloat16 h = __float2bfloat16(v);
    hi[i] = h;
    lo[i] = __float2bfloat16(v - __bfloat162float(h));
}

// ---------------- embedding + PE ----------------
__global__ void embed_enc(const int* __restrict__ x, const float* __restrict__ emb,
                          float* __restrict__ e, __nv_bfloat16* __restrict__ ehi,
                          __nv_bfloat16* __restrict__ elo) {
    int idx = blockIdx.x*blockDim.x + threadIdx.x;
    if (idx >= Bz*Sz*Dm) return;
    int d  = idx % Dm;
    int bs = idx / Dm;
    int s  = bs % Sz;
    int tok = x[bs];
    float div = exp2f(-(float)(d & ~1) * (13.287712379549449f / (float)Dm));
    float arg = (float)s * div;
    float pe = (d & 1) ? cosf(arg) : sinf(arg);
    float v = emb[tok*Dm + d] * 22.627416997969522f + pe;
    e[idx] = v;
    __nv_bfloat16 h = __float2bfloat16(v);
    ehi[idx] = h;
    elo[idx] = __float2bfloat16(v - __bfloat162float(h));
}

__global__ void embed_dec(const int* __restrict__ tgt, const float* __restrict__ emb,
                          float* __restrict__ o) {
    int idx = blockIdx.x*blockDim.x + threadIdx.x;
    if (idx >= Bz*Dm) return;
    int d = idx % Dm;
    int b = idx / Dm;
    float pe = (d & 1) ? 1.f : 0.f;
    o[idx] = emb[tgt[b]*Dm + d] * 22.627416997969522f + pe;
}

// ============ 3-stage pipelined mma.sync GEMM (bf16x3, big tiles) ===========
template<int BN_, int EPI, int WMODE>
__global__ void __launch_bounds__(BN_ == 128 ? 256 : 128, 1)
gemm_mma(const __nv_bfloat16* __restrict__ Agh, const __nv_bfloat16* __restrict__ Agl,
         const __nv_bfloat16* __restrict__ Bgh, const __nv_bfloat16* __restrict__ Bgl,
         const float* __restrict__ bias,
         float* __restrict__ C, __nv_bfloat16* __restrict__ Chi,
         __nv_bfloat16* __restrict__ Clo,
         int K, int lda, int ldb, int ldc,
         int zdiv, long long sA1, long long sA2, long long sB1, long long sB2,
         long long sC1, long long sC2, long long sBias1, long long sBias2) {
    constexpr int NT   = (BN_ == 128) ? 256 : 128;
    constexpr int ASTG = 128 * 40;
    constexpr int BLD  = BN_ + 8;
    constexpr int BSTG = 32 * BLD;

    extern __shared__ __nv_bfloat16 sm[];
    __nv_bfloat16* Ah = sm;
    __nv_bfloat16* Al = Ah + 3*ASTG;
    __nv_bfloat16* Bh = Al + 3*ASTG;
    __nv_bfloat16* Bl = Bh + 3*BSTG;

    int z = blockIdx.z, z1 = z / zdiv, z2 = z % zdiv;
    const __nv_bfloat16* Abh = Agh + z1*sA1 + z2*sA2;
    const __nv_bfloat16* Abl = Agl + z1*sA1 + z2*sA2;
    const __nv_bfloat16* Bbh = Bgh + z1*sB1 + z2*sB2;
    const __nv_bfloat16* Bbl = Bgl + z1*sB1 + z2*sB2;
    long long coff = z1*sC1 + z2*sC2;

    int m0 = blockIdx.y * 128, n0 = blockIdx.x * BN_;
    int tid = threadIdx.x, lane = tid & 31, wid = tid >> 5;
    int wm = wid & 1, wn = wid >> 1;
    int gid = lane >> 2, tig = lane & 3;

    auto load_stage = [&](int st, int kt) {
        int k0 = kt * 32;
        for (int idx = tid; idx < 512; idx += NT) {
            int r = idx >> 2, c = (idx & 3) * 8;
            int so = st*ASTG + r*40 + c;
            cpa16(Ah + so, Abh + (size_t)(m0 + r)*lda + k0 + c);
            cpa16(Al + so, Abl + (size_t)(m0 + r)*lda + k0 + c);
        }
        constexpr int CH = BN_ / 8;
        for (int idx = tid; idx < 32*CH; idx += NT) {
            int r = idx / CH, c = (idx % CH) * 8;
            int so = st*BSTG + r*BLD + c;
            cpa16(Bh + so, Bbh + (size_t)(k0 + r)*ldb + n0 + c);
            cpa16(Bl + so, Bbl + (size_t)(k0 + r)*ldb + n0 + c);
        }
    };

    float acc[4][4][4] = {};
    const int KT = K >> 5;

    load_stage(0, 0); CP_COMMIT();
    if (KT > 1) { load_stage(1, 1); CP_COMMIT(); }
    if (KT > 1) asm volatile("cp.async.wait_group 1;\n" ::: "memory");
    else        asm volatile("cp.async.wait_group 0;\n" ::: "memory");
    __syncthreads();

    for (int c = 0; c < KT; c++) {
        int st = c % 3;
        const __nv_bfloat16* a_h = Ah + st*ASTG;
        const __nv_bfloat16* a_l = Al + st*ASTG;
        const __nv_bfloat16* b_h = Bh + st*BSTG;
        const __nv_bfloat16* b_l = Bl + st*BSTG;

#pragma unroll
        for (int kk = 0; kk < 2; kk++) {
            int kc = kk*16 + ((lane >> 4) << 3);
            uint32_t ah[4][4], al[4][4], bh[4][2], bl[4][2];
#pragma unroll
            for (int mi = 0; mi < 4; mi++) {
                int ar = wm*64 + mi*16 + (lane & 15);
                ldsm4(ah[mi][0], ah[mi][1], ah[mi][2], ah[mi][3], a_h + ar*40 + kc);
                ldsm4(al[mi][0], al[mi][1], al[mi][2], al[mi][3], a_l + ar*40 + kc);
            }
#pragma unroll
            for (int ng = 0; ng < 2; ng++) {
                uint32_t r0, r1, r2, r3;
                int rr = kk*16 + ((lane >> 4) << 3) + (lane & 7);
                int cc = wn*32 + ng*16 + (((lane >> 3) & 1) << 3);
                ldsm4t(r0, r1, r2, r3, b_h + rr*BLD + cc);
                bh[ng*2  ][0] = r0; bh[ng*2  ][1] = r2;
                bh[ng*2+1][0] = r1; bh[ng*2+1][1] = r3;
                ldsm4t(r0, r1, r2, r3, b_l + rr*BLD + cc);
                bl[ng*2  ][0] = r0; bl[ng*2  ][1] = r2;
                bl[ng*2+1][0] = r1; bl[ng*2+1][1] = r3;
            }
#pragma unroll
            for (int mi = 0; mi < 4; mi++)
#pragma unroll
                for (int ni = 0; ni < 4; ni++) mma_bf16(acc[mi][ni], ah[mi], bh[ni]);
#pragma unroll
            for (int mi = 0; mi < 4; mi++)
#pragma unroll
                for (int ni = 0; ni < 4; ni++) mma_bf16(acc[mi][ni], ah[mi], bl[ni]);
#pragma unroll
            for (int mi = 0; mi < 4; mi++)
#pragma unroll
                for (int ni = 0; ni < 4; ni++) mma_bf16(acc[mi][ni], al[mi], bh[ni]);
        }

        if (c + 2 < KT) {
            load_stage((c + 2) % 3, c + 2);
            CP_COMMIT();
            asm volatile("cp.async.wait_group 1;\n" ::: "memory");
            __syncthreads();
        } else if (c + 1 < KT) {
            asm volatile("cp.async.wait_group 0;\n" ::: "memory");
            __syncthreads();
        }
    }

    const float* biasb = (EPI <= 1) ? bias + z1*sBias1 + z2*sBias2 : nullptr;
#pragma unroll
    for (int mi = 0; mi < 4; mi++)
#pragma unroll
        for (int ni = 0; ni < 4; ni++) {
            int row = m0 + wm*64 + mi*16 + gid;
            int col = n0 + wn*32 + ni*8 + tig*2;
#pragma unroll
            for (int e2 = 0; e2 < 4; e2++) {
                int r  = row + (e2 >> 1)*8;
                int cc = col + (e2 & 1);
                float v = acc[mi][ni][e2];
                if (EPI == 0 || EPI == 1) v += biasb[cc];
                if (EPI == 1) v = fmaxf(v, 0.f);
                size_t idx = (size_t)(coff + (long long)r*ldc + cc);
                if (WMODE & 1) C[idx] = v;
                if (WMODE & 2) {
                    __nv_bfloat16 h = __float2bfloat16(v);
                    Chi[idx] = h;
                    Clo[idx] = __float2bfloat16(v - __bfloat162float(h));
                }
            }
        }
}

// ============ fused scores + mask + softmax + split =========================
__global__ void __launch_bounds__(256)
scores_softmax(const __nv_bfloat16* __restrict__ qh, const __nv_bfloat16* __restrict__ ql,
               const __nv_bfloat16* __restrict__ kh, const __nv_bfloat16* __restrict__ kl,
               __nv_bfloat16* __restrict__ phi, __nv_bfloat16* __restrict__ plo) {
    extern __shared__ __nv_bfloat16 sm[];
    __nv_bfloat16* Qh = sm;                 // 64*72
    __nv_bfloat16* Ql = Qh + 64*72;
    __nv_bfloat16* Kh = Ql + 64*72;         // 512*72
    __nv_bfloat16* Kl = Kh + 512*72;

    int bh = blockIdx.y, b = bh >> 3, h = bh & 7;
    int q0 = blockIdx.x * 64;
    int tid = threadIdx.x, lane = tid & 31, wid = tid >> 5;
    int wm = wid & 1, wn = wid >> 1;
    int gid = lane >> 2, tig = lane & 3;

    for (int idx = tid; idx < 512; idx += 256) {
        int r = idx >> 3, c = (idx & 7) * 8;
        size_t go = (size_t)(b*Sz + q0 + r)*Dm + h*DKh + c;
        cpa16(Qh + r*72 + c, qh + go);
        cpa16(Ql + r*72 + c, ql + go);
    }
    for (int idx = tid; idx < 4096; idx += 256) {
        int r = idx >> 3, c = (idx & 7) * 8;
        size_t go = (size_t)(b*Sz + r)*Dm + h*DKh + c;
        cpa16(Kh + r*72 + c, kh + go);
        cpa16(Kl + r*72 + c, kl + go);
    }
    CP_COMMIT();
    asm volatile("cp.async.wait_group 0;\n" ::: "memory");
    __syncthreads();

    float acc[2][16][4] = {};
#pragma unroll
    for (int kk = 0; kk < 4; kk++) {
        int kc = kk*16 + ((lane >> 4) << 3);
        uint32_t ah[2][4], al[2][4];
#pragma unroll
        for (int mi = 0; mi < 2; mi++) {
            int ar = wm*32 + mi*16 + (lane & 15);
            ldsm4(ah[mi][0], ah[mi][1], ah[mi][2], ah[mi][3], Qh + ar*72 + kc);
            ldsm4(al[mi][0], al[mi][1], al[mi][2], al[mi][3], Ql + ar*72 + kc);
        }
#pragma unroll
        for (int ng = 0; ng < 8; ng++) {
            int br = wn*128 + ng*16 + (lane & 15);
            uint32_t r0, r1, r2, r3;
            uint32_t bhf[2][2], blf[2][2];
            ldsm4(r0, r1, r2, r3, Kh + br*72 + kc);
            bhf[0][0] = r0; bhf[0][1] = r2; bhf[1][0] = r1; bhf[1][1] = r3;
            ldsm4(r0, r1, r2, r3, Kl + br*72 + kc);
            blf[0][0] = r0; blf[0][1] = r2; blf[1][0] = r1; blf[1][1] = r3;
#pragma unroll
            for (int mi = 0; mi < 2; mi++)
#pragma unroll
                for (int sub = 0; sub < 2; sub++) {
                    mma_bf16(acc[mi][ng*2+sub], ah[mi], bhf[sub]);
                    mma_bf16(acc[mi][ng*2+sub], ah[mi], blf[sub]);
                    mma_bf16(acc[mi][ng*2+sub], al[mi], bhf[sub]);
                }
        }
    }
    __syncthreads();
    float* rmax = (float*)sm;        // [64][4]
    float* rsum = rmax + 256;        // [64][4]

#pragma unroll
    for (int mi = 0; mi < 2; mi++)
#pragma unroll
        for (int rh = 0; rh < 2; rh++) {
            float m1 = -INFINITY;
#pragma unroll
            for (int ni = 0; ni < 16; ni++)
#pragma unroll
                for (int nj = 0; nj < 2; nj++) {
                    float v = acc[mi][ni][rh*2+nj] * 0.125f;
                    if (v == 0.f) v = NEGV;
                    acc[mi][ni][rh*2+nj] = v;
                    m1 = fmaxf(m1, v);
                }
            m1 = fmaxf(m1, __shfl_xor_sync(0xffffffffu, m1, 1));
            m1 = fmaxf(m1, __shfl_xor_sync(0xffffffffu, m1, 2));
            int row = wm*32 + mi*16 + rh*8 + gid;
            if (tig == 0) rmax[row*4 + wn] = m1;
        }
    __syncthreads();
#pragma unroll
    for (int mi = 0; mi < 2; mi++)
#pragma unroll
        for (int rh = 0; rh < 2; rh++) {
            int row = wm*32 + mi*16 + rh*8 + gid;
            float mx = fmaxf(fmaxf(rmax[row*4+0], rmax[row*4+1]),
                             fmaxf(rmax[row*4+2], rmax[row*4+3]));
            float s1 = 0.f;
#pragma unroll
            for (int ni = 0; ni < 16; ni++)
#pragma unroll
                for (int nj = 0; nj < 2; nj++) {
                    float v = __expf(acc[mi][ni][rh*2+nj] - mx);
                    acc[mi][ni][rh*2+nj] = v;
                    s1 += v;
                }
            s1 += __shfl_xor_sync(0xffffffffu, s1, 1);
            s1 += __shfl_xor_sync(0xffffffffu, s1, 2);
            if (tig == 0) rsum[row*4 + wn] = s1;
        }
    __syncthreads();
#pragma unroll
    for (int mi = 0; mi < 2; mi++)
#pragma unroll
        for (int rh = 0; rh < 2; rh++) {
            int row = wm*32 + mi*16 + rh*8 + gid;
            float inv = 1.f / (rsum[row*4+0] + rsum[row*4+1] + rsum[row*4+2] + rsum[row*4+3]);
            size_t base = ((size_t)bh*Sz + q0 + row)*Sz;
#pragma unroll
            for (int ni = 0; ni < 16; ni++) {
                int col = wn*128 + (ni>>1)*16 + (ni&1)*8 + tig*2;
                float v0 = acc[mi][ni][rh*2+0] * inv;
                float v1 = acc[mi][ni][rh*2+1] * inv;
                __nv_bfloat16 h0 = __float2bfloat16(v0);
                __nv_bfloat16 h1 = __float2bfloat16(v1);
                __nv_bfloat16 l0 = __float2bfloat16(v0 - __bfloat162float(h0));
                __nv_bfloat16 l1 = __float2bfloat16(v1 - __bfloat162float(h1));
                uint32_t ph = ((uint32_t)*(uint16_t*)&h1 << 16) | *(uint16_t*)&h0;
                uint32_t pl = ((uint32_t)*(uint16_t*)&l1 << 16) | *(uint16_t*)&l0;
                *(uint32_t*)(phi + base + col) = ph;
                *(uint32_t*)(plo + base + col) = pl;
            }
        }
}

// ---------------- out = LayerNorm(a + res) (+ optional split) ---------------
template<int SPLIT>
__global__ void add_ln(const float* __restrict__ a, const float* __restrict__ res,
                       const float* __restrict__ g, const float* __restrict__ beta,
                       float* __restrict__ out, __nv_bfloat16* __restrict__ ohi,
                       __nv_bfloat16* __restrict__ olo) {
    size_t row = blockIdx.x;
    int tid = threadIdx.x;
    int c = tid * 4;
    float4 av = *(const float4*)&a[row*Dm + c];
    float4 rv = *(const float4*)&res[row*Dm + c];
    float4 x;
    x.x = av.x + rv.x; x.y = av.y + rv.y; x.z = av.z + rv.z; x.w = av.w + rv.w;
    float s  = x.x + x.y + x.z + x.w;
    float s2 = x.x*x.x + x.y*x.y + x.z*x.z + x.w*x.w;
#pragma unroll
    for (int o = 16; o; o >>= 1) {
        s  += __shfl_xor_sync(0xffffffffu, s,  o);
        s2 += __shfl_xor_sync(0xffffffffu, s2, o);
    }
    __shared__ float sm[4], sq[4];
    if ((tid & 31) == 0) { sm[tid>>5] = s; sq[tid>>5] = s2; }
    __syncthreads();
    s  = sm[0] + sm[1] + sm[2] + sm[3];
    s2 = sq[0] + sq[1] + sq[2] + sq[3];
    float mean = s * (1.f/Dm);
    float var  = s2 * (1.f/Dm) - mean*mean;
    float inv  = rsqrtf(var + 1e-5f);
    float4 gv = *(const float4*)&g[c];
    float4 bv = *(const float4*)&beta[c];
    float y[4];
    y[0] = (x.x - mean)*inv*gv.x + bv.x;
    y[1] = (x.y - mean)*inv*gv.y + bv.y;
    y[2] = (x.z - mean)*inv*gv.z + bv.z;
    y[3] = (x.w - mean)*inv*gv.w + bv.w;
    *(float4*)&out[row*Dm + c] = *(float4*)y;
    if (SPLIT) {
        __nv_bfloat16 hh[4], ll[4];
#pragma unroll
        for (int j = 0; j < 4; j++) {
            hh[j] = __float2bfloat16(y[j]);
            ll[j] = __float2bfloat16(y[j] - __bfloat162float(hh[j]));
        }
        *(uint2*)&ohi[row*Dm + c] = *(uint2*)hh;
        *(uint2*)&olo[row*Dm + c] = *(uint2*)ll;
    }
}

// ---------------- decoder cross-attention (Sq=1, f32) ----------------
__global__ void cross_attn(const float* __restrict__ q, const float* __restrict__ k,
                           const float* __restrict__ v, float* __restrict__ o) {
    int h = blockIdx.x, b = blockIdx.y;
    __shared__ float qv[64];
    __shared__ float p[512];
    __shared__ float red[8];
    int tid = threadIdx.x;
    if (tid < 64) qv[tid] = q[b*Dm + h*DKh + tid];
    __syncthreads();
    float sc[2];
    float lmax = -INFINITY;
#pragma unroll
    for (int it = 0; it < 2; it++) {
        int j = tid + it*256;
        const float* kp = &k[(size_t)(b*Sz + j)*Dm + h*DKh];
        float s = 0.f;
#pragma unroll
        for (int c = 0; c < 64; c++) s += qv[c] * kp[c];
        s *= 0.125f;
        if (s == 0.f) s = NEGV;
        sc[it] = s;
        lmax = fmaxf(lmax, s);
    }
#pragma unroll
    for (int off = 16; off; off >>= 1) lmax = fmaxf(lmax, __shfl_xor_sync(0xffffffffu, lmax, off));
    if ((tid & 31) == 0) red[tid >> 5] = lmax;
    __syncthreads();
    float mx = red[0];
#pragma unroll
    for (int w = 1; w < 8; w++) mx = fmaxf(mx, red[w]);
    __syncthreads();
    float lsum = 0.f;
#pragma unroll
    for (int it = 0; it < 2; it++) {
        float e = __expf(sc[it] - mx);
        p[tid + it*256] = e;
        lsum += e;
    }
#pragma unroll
    for (int off = 16; off; off >>= 1) lsum += __shfl_xor_sync(0xffffffffu, lsum, off);
    if ((tid & 31) == 0) red[tid >> 5] = lsum;
    __syncthreads();
    float sum = red[0] + red[1] + red[2] + red[3] + red[4] + red[5] + red[6] + red[7];
    float inv = 1.f / sum;
    int warp = tid >> 5, lane = tid & 31;
#pragma unroll
    for (int dd = 0; dd < 8; dd++) {
        int d = warp*8 + dd;
        float acc = 0.f;
        for (int j = lane; j < Sz; j += 32)
            acc += p[j] * v[(size_t)(b*Sz + j)*Dm + h*DKh + d];
#pragma unroll
        for (int off = 16; off; off >>= 1) acc += __shfl_xor_sync(0xffffffffu, acc, off);
        if (lane == 0) o[b*Dm + h*DKh + d] = acc * inv;
    }
}

// ---------- tiny-M (M=8) GEMM, K-parallel: 512 thr = 64 cols x 8 K-slices ---
template<int RELU>
__global__ void __launch_bounds__(512)
gemm8w(const float* __restrict__ A, const float* __restrict__ W,
       const float* __restrict__ bias, float* __restrict__ C, int K, int N) {
    __shared__ float red[8][8][64];
    int t = threadIdx.x;
    int cl = t & 63;
    int col = blockIdx.x*64 + cl;
    int sl = t >> 6;
    float acc[8] = {};
    if (col < N) {
        int kn = K >> 3;
        int k0 = sl * kn, k1 = k0 + kn;
        for (int k = k0; k < k1; k++) {
            float wv = W[(size_t)k*N + col];
#pragma unroll
            for (int r = 0; r < 8; r++) acc[r] += A[r*K + k] * wv;
        }
    }
#pragma unroll
    for (int r = 0; r < 8; r++) red[r][sl][cl] = acc[r];
    __syncthreads();
    if (t < 64 && col < N) {
        float bv = bias[col];
#pragma unroll
        for (int r = 0; r < 8; r++) {
            float s = 0.f;
#pragma unroll
            for (int s8 = 0; s8 < 8; s8++) s += red[r][s8][t];
            float val = s + bv;
            if (RELU) val = fmaxf(val, 0.f);
            C[r*N + col] = val;
        }
    }
}

// ---------------- host orchestration ----------------
extern "C" void kernel_launch(void* const* d_in, const int* in_sizes, int n_in,
                              void* d_out, int out_size) {
    const int*   x        = (const int*)d_in[0];
    const int*   tgt      = (const int*)d_in[1];
    const float* in_emb   = (const float*)d_in[2];
    const float* out_emb  = (const float*)d_in[3];
    const float* enc_qkv_w = (const float*)d_in[4];
    const float* enc_qkv_b = (const float*)d_in[5];
    const float* enc_ln1_g = (const float*)d_in[6];
    const float* enc_ln1_b = (const float*)d_in[7];
    const float* enc_ffn1_w = (const float*)d_in[8];
    const float* enc_ffn1_b = (const float*)d_in[9];
    const float* enc_ffn2_w = (const float*)d_in[10];
    const float* enc_ffn2_b = (const float*)d_in[11];
    const float* enc_ln2_g = (const float*)d_in[12];
    const float* enc_ln2_b = (const float*)d_in[13];
    const float* dec_qkv1_w = (const float*)d_in[14];
    const float* dec_qkv1_b = (const float*)d_in[15];
    const float* dec_ln1_g = (const float*)d_in[16];
    const float* dec_ln1_b = (const float*)d_in[17];
    const float* dec_qkv2_w = (const float*)d_in[18];
    const float* dec_qkv2_b = (const float*)d_in[19];
    const float* dec_ln2_g = (const float*)d_in[20];
    const float* dec_ln2_b = (const float*)d_in[21];
    const float* dec_ffn1_w = (const float*)d_in[22];
    const float* dec_ffn1_b = (const float*)d_in[23];
    const float* dec_ffn2_w = (const float*)d_in[24];
    const float* dec_ffn2_b = (const float*)d_in[25];
    const float* dec_ln3_g = (const float*)d_in[26];
    const float* dec_ln3_b = (const float*)d_in[27];
    const float* out_w = (const float*)d_in[28];
    const float* out_b = (const float*)d_in[29];

    float *e, *attn, *tbuf, *dbuf, *dq, *dt, *dh, *kvf;
    __nv_bfloat16 *ehi, *elo, *qkvh, *qkvl, *schi, *sclo, *hhi, *hlo;
    __nv_bfloat16 *wqkvh, *wqkvl, *wf1h, *wf1l, *wf2h, *wf2l, *wd2h, *wd2l;
    cudaGetSymbolAddress((void**)&e,    g_e);
    cudaGetSymbolAddress((void**)&ehi,  g_ehi);
    cudaGetSymbolAddress((void**)&elo,  g_elo);
    cudaGetSymbolAddress((void**)&qkvh, g_qkvh);
    cudaGetSymbolAddress((void**)&qkvl, g_qkvl);
    cudaGetSymbolAddress((void**)&kvf,  g_kvf);
    cudaGetSymbolAddress((void**)&schi, g_schi);
    cudaGetSymbolAddress((void**)&sclo, g_sclo);
    cudaGetSymbolAddress((void**)&attn, g_attn);
    cudaGetSymbolAddress((void**)&hhi,  g_hhi);
    cudaGetSymbolAddress((void**)&hlo,  g_hlo);
    cudaGetSymbolAddress((void**)&tbuf, g_t);
    cudaGetSymbolAddress((void**)&dbuf, g_d);
    cudaGetSymbolAddress((void**)&dq,   g_dq);
    cudaGetSymbolAddress((void**)&dt,   g_dt);
    cudaGetSymbolAddress((void**)&dh,   g_dh);
    cudaGetSymbolAddress((void**)&wqkvh, g_wqkvh);
    cudaGetSymbolAddress((void**)&wqkvl, g_wqkvl);
    cudaGetSymbolAddress((void**)&wf1h, g_wf1h);
    cudaGetSymbolAddress((void**)&wf1l, g_wf1l);
    cudaGetSymbolAddress((void**)&wf2h, g_wf2h);
    cudaGetSymbolAddress((void**)&wf2l, g_wf2l);
    cudaGetSymbolAddress((void**)&wd2h, g_wd2h);
    cudaGetSymbolAddress((void**)&wd2l, g_wd2l);

    const int M = Bz*Sz;            // 4096
    const long long DD = (long long)Dm*Dm;
    const long long MD = (long long)M*Dm;
    const long long SS = (long long)Sz*Sz;
    const long long SDm = (long long)Sz*Dm;

    const int SM_TB0_128 = 61440 + 2*3*32*136*2;   // 113664
    const int SM_TB0_64  = 61440 + 2*3*32*72*2;    //  89088
    const int SM_SCORES  = (64*72*2 + 512*72*2) * 2;  // 165888
    cudaFuncSetAttribute(gemm_mma<128,0,2>, cudaFuncAttributeMaxDynamicSharedMemorySize, SM_TB0_128);
    cudaFuncSetAttribute(gemm_mma<64,3,1>,  cudaFuncAttributeMaxDynamicSharedMemorySize, SM_TB0_64);
    cudaFuncSetAttribute(gemm_mma<128,1,2>, cudaFuncAttributeMaxDynamicSharedMemorySize, SM_TB0_128);
    cudaFuncSetAttribute(gemm_mma<128,0,1>, cudaFuncAttributeMaxDynamicSharedMemorySize, SM_TB0_128);
    cudaFuncSetAttribute(scores_softmax,    cudaFuncAttributeMaxDynamicSharedMemorySize, SM_SCORES);

    // ---- split weights once per launch ----
    {
        int n1 = Lz*3*Dm*Dm;
        splitk<<<(n1+255)/256, 256>>>(enc_qkv_w, wqkvh, wqkvl, n1);
        int n2 = Lz*Dm*DFFz;
        splitk<<<(n2+255)/256, 256>>>(enc_ffn1_w, wf1h, wf1l, n2);
        splitk<<<(n2+255)/256, 256>>>(enc_ffn2_w, wf2h, wf2l, n2);
        splitk<<<(n1+255)/256, 256>>>(dec_qkv2_w, wd2h, wd2l, n1);
    }

    // ---------------- encoder ----------------
    embed_enc<<<(Bz*Sz*Dm + 255)/256, 256>>>(x, in_emb, e, ehi, elo);
    for (int i = 0; i < Lz; i++) {
        gemm_mma<128,0,2><<<dim3(Dm/128, M/128, 3), 256, SM_TB0_128>>>(
            ehi, elo, wqkvh + (size_t)i*3*DD, wqkvl + (size_t)i*3*DD,
            enc_qkv_b + (size_t)i*3*Dm, nullptr, qkvh, qkvl,
            Dm, Dm, Dm, Dm,
            1, 0, 0, DD, 0, MD, 0, Dm, 0);
        scores_softmax<<<dim3(Sz/64, Bz*Hn), 256, SM_SCORES>>>(
            qkvh, qkvl, qkvh + MD, qkvl + MD, schi, sclo);
        gemm_mma<64,3,1><<<dim3(1, Sz/128, Bz*Hn), 128, SM_TB0_64>>>(
            schi, sclo, qkvh + 2*MD, qkvl + 2*MD, nullptr, attn, nullptr, nullptr,
            Sz, Sz, Dm, Dm,
            Hn, (long long)Hn*SS, SS, SDm, DKh, SDm, DKh, 0, 0);
        add_ln<1><<<M, 128>>>(attn, e, enc_ln1_g + i*Dm, enc_ln1_b + i*Dm, e, ehi, elo);
        gemm_mma<128,1,2><<<dim3(DFFz/128, M/128, 1), 256, SM_TB0_128>>>(
            ehi, elo, wf1h + (size_t)i*Dm*DFFz, wf1l + (size_t)i*Dm*DFFz,
            enc_ffn1_b + (size_t)i*DFFz, nullptr, hhi, hlo,
            Dm, Dm, DFFz, DFFz,
            1, 0, 0, 0, 0, 0, 0, 0, 0);
        gemm_mma<128,0,1><<<dim3(Dm/128, M/128, 1), 256, SM_TB0_128>>>(
            hhi, hlo, wf2h + (size_t)i*DFFz*Dm, wf2l + (size_t)i*DFFz*Dm,
            enc_ffn2_b + (size_t)i*Dm, tbuf, nullptr, nullptr,
            DFFz, DFFz, Dm, Dm,
            1, 0, 0, 0, 0, 0, 0, 0, 0);
        add_ln<1><<<M, 128>>>(tbuf, e, enc_ln2_g + i*Dm, enc_ln2_b + i*Dm, e, ehi, elo);
    }

    // ---- batched decoder cross K/V for ALL layers: z = Lz*2 = 12 ----
    // z1 = layer (0..5), z2 = 0(K)/1(V); weight slot = 3*z1 + 1 + z2
    gemm_mma<128,0,1><<<dim3(Dm/128, M/128, Lz*2), 256, SM_TB0_128>>>(
        ehi, elo, wd2h + DD, wd2l + DD,
        dec_qkv2_b + Dm, kvf, nullptr, nullptr,
        Dm, Dm, Dm, Dm,
        2, 0, 0, 3*DD, DD, 2*MD, MD, 3*(long long)Dm, Dm);

    // ---------------- decoder (seq len 1; self-attn == V projection) --------
    embed_dec<<<(Bz*Dm + 255)/256, 256>>>(tgt, out_emb, dbuf);
    for (int i = 0; i < Lz; i++) {
        gemm8w<0><<<Dm/64, 512>>>(dbuf, dec_qkv1_w + (size_t)(i*3+2)*DD, dec_qkv1_b + (i*3+2)*Dm, dt, Dm, Dm);
        add_ln<0><<<Bz, 128>>>(dt, dbuf, dec_ln1_g + i*Dm, dec_ln1_b + i*Dm, dbuf, nullptr, nullptr);
        gemm8w<0><<<Dm/64, 512>>>(dbuf, dec_qkv2_w + (size_t)(i*3+0)*DD, dec_qkv2_b + (i*3+0)*Dm, dq, Dm, Dm);
        cross_attn<<<dim3(Hn, Bz), 256>>>(dq, kvf + (size_t)i*2*MD /*K*/, kvf + (size_t)i*2*MD + MD /*V*/, dt);
        add_ln<0><<<Bz, 128>>>(dt, dbuf, dec_ln2_g + i*Dm, dec_ln2_b + i*Dm, dbuf, nullptr, nullptr);
        gemm8w<1><<<DFFz/64, 512>>>(dbuf, dec_ffn1_w + (size_t)i*Dm*DFFz, dec_ffn1_b + i*DFFz, dh, Dm, DFFz);
        gemm8w<0><<<Dm/64, 512>>>(dh, dec_ffn2_w + (size_t)i*DFFz*Dm, dec_ffn2_b + i*Dm, dt, DFFz, Dm);
        add_ln<0><<<Bz, 128>>>(dt, dbuf, dec_ln3_g + i*Dm, dec_ln3_b + i*Dm, dbuf, nullptr, nullptr);
    }

    // output projection -> d_out [8,1,1000]
    gemm8w<0><<<(OUTz+63)/64, 512>>>(dbuf, out_w, out_b, (float*)d_out, Dm, OUTz);
    (void)in_sizes; (void)n_in; (void)out_size;
}

// round 10
// speedup vs baseline: 3.4681x; 1.5584x over previous
#include <cuda_runtime.h>
#include <cuda_fp16.h>
#include <math.h>
#include <stdint.h>

#define Bz   8
#define Sz   512
#define Dm   512
#define Hn   8
#define DKh  64
#define Lz   6
#define DFFz 2048
#define OUTz 1000
#define NEGV (-1e9f)

// ---------------- scratch (device globals) ----------------
__device__ float g_e[Bz*Sz*Dm];
__device__ __half g_eh[Bz*Sz*Dm];
__device__ __half g_qkvh[3*Bz*Sz*Dm];
__device__ float g_kvf[(size_t)Lz*2*Bz*Sz*Dm];
__device__ __half g_sch[(size_t)Bz*Hn*Sz*Sz];
__device__ float g_attn[Bz*Sz*Dm];
__device__ __half g_hh[Bz*Sz*DFFz];
__device__ float g_t[Bz*Sz*Dm];
__device__ float g_d[Bz*Dm];
__device__ float g_dq[Bz*Dm];
__device__ float g_dt[Bz*Dm];
__device__ float g_dh[Bz*DFFz];
// fp16 weights in original [K,N] layout
__device__ __half g_wqkvh[Lz*3*Dm*Dm];
__device__ __half g_wf1h[Lz*Dm*DFFz];
__device__ __half g_wf2h[Lz*DFFz*Dm];
__device__ __half g_wd2h[Lz*3*Dm*Dm];

// ---------------- helpers ----------------
__device__ __forceinline__ void cpa16(void* dst, const void* src) {
    uint32_t d = (uint32_t)__cvta_generic_to_shared(dst);
    asm volatile("cp.async.ca.shared.global [%0], [%1], 16;\n" :: "r"(d), "l"(src));
}
#define CP_COMMIT() asm volatile("cp.async.commit_group;\n" ::: "memory")
__device__ __forceinline__ void ldsm4(uint32_t& r0, uint32_t& r1, uint32_t& r2, uint32_t& r3,
                                      const void* p) {
    uint32_t a = (uint32_t)__cvta_generic_to_shared(p);
    asm volatile("ldmatrix.sync.aligned.m8n8.x4.shared.b16 {%0,%1,%2,%3}, [%4];\n"
                 : "=r"(r0), "=r"(r1), "=r"(r2), "=r"(r3) : "r"(a));
}
__device__ __forceinline__ void ldsm4t(uint32_t& r0, uint32_t& r1, uint32_t& r2, uint32_t& r3,
                                       const void* p) {
    uint32_t a = (uint32_t)__cvta_generic_to_shared(p);
    asm volatile("ldmatrix.sync.aligned.m8n8.x4.trans.shared.b16 {%0,%1,%2,%3}, [%4];\n"
                 : "=r"(r0), "=r"(r1), "=r"(r2), "=r"(r3) : "r"(a));
}
__device__ __forceinline__ void mma_f16(float c[4], const uint32_t a[4], const uint32_t b[2]) {
    asm volatile(
        "mma.sync.aligned.m16n8k16.row.col.f32.f16.f16.f32 "
        "{%0,%1,%2,%3}, {%4,%5,%6,%7}, {%8,%9}, {%0,%1,%2,%3};\n"
        : "+f"(c[0]), "+f"(c[1]), "+f"(c[2]), "+f"(c[3])
        : "r"(a[0]), "r"(a[1]), "r"(a[2]), "r"(a[3]), "r"(b[0]), "r"(b[1]));
}

// ---------------- convert f32 -> fp16 ----------------
__global__ void convh(const float* __restrict__ src, __half* __restrict__ dst, int n) {
    int i = blockIdx.x*blockDim.x + threadIdx.x;
    if (i >= n) return;
    dst[i] = __float2half(src[i]);
}

// ---------------- embedding + PE ----------------
__global__ void embed_enc(const int* __restrict__ x, const float* __restrict__ emb,
                          float* __restrict__ e, __half* __restrict__ eh) {
    int idx = blockIdx.x*blockDim.x + threadIdx.x;
    if (idx >= Bz*Sz*Dm) return;
    int d  = idx % Dm;
    int bs = idx / Dm;
    int s  = bs % Sz;
    int tok = x[bs];
    float div = exp2f(-(float)(d & ~1) * (13.287712379549449f / (float)Dm));
    float arg = (float)s * div;
    float pe = (d & 1) ? cosf(arg) : sinf(arg);
    float v = emb[tok*Dm + d] * 22.627416997969522f + pe;
    e[idx] = v;
    eh[idx] = __float2half(v);
}

__global__ void embed_dec(const int* __restrict__ tgt, const float* __restrict__ emb,
                          float* __restrict__ o) {
    int idx = blockIdx.x*blockDim.x + threadIdx.x;
    if (idx >= Bz*Dm) return;
    int d = idx % Dm;
    int b = idx / Dm;
    float pe = (d & 1) ? 1.f : 0.f;
    o[idx] = emb[tgt[b]*Dm + d] * 22.627416997969522f + pe;
}

// ============ 3-stage pipelined mma.sync GEMM (fp16, big tiles) =============
// C[M,N] = A[M,K] @ B[K,N]; A fp16 [M,K], B fp16 [K,N] (ldmatrix.trans).
// BM=128; BN_=128 -> 256 thr (2m x 4n); BN_=64 -> 128 thr (2m x 2n).
// EPI: 0=+bias, 1=+bias+relu, 3=none.  WMODE bit0: f32 C; bit1: fp16 Ch.
template<int BN_, int EPI, int WMODE>
__global__ void __launch_bounds__(BN_ == 128 ? 256 : 128)
gemm_mma(const __half* __restrict__ Ag, const __half* __restrict__ Bg,
         const float* __restrict__ bias,
         float* __restrict__ C, __half* __restrict__ Ch,
         int K, int lda, int ldb, int ldc,
         int zdiv, long long sA1, long long sA2, long long sB1, long long sB2,
         long long sC1, long long sC2, long long sBias1, long long sBias2) {
    constexpr int NT   = (BN_ == 128) ? 256 : 128;
    constexpr int ASTG = 128 * 40;
    constexpr int BLD  = BN_ + 8;
    constexpr int BSTG = 32 * BLD;

    extern __shared__ __half sm[];
    __half* Ah = sm;
    __half* Bh = Ah + 3*ASTG;

    int z = blockIdx.z, z1 = z / zdiv, z2 = z % zdiv;
    const __half* Ab = Ag + z1*sA1 + z2*sA2;
    const __half* Bb = Bg + z1*sB1 + z2*sB2;
    long long coff = z1*sC1 + z2*sC2;

    int m0 = blockIdx.y * 128, n0 = blockIdx.x * BN_;
    int tid = threadIdx.x, lane = tid & 31, wid = tid >> 5;
    int wm = wid & 1, wn = wid >> 1;
    int gid = lane >> 2, tig = lane & 3;

    auto load_stage = [&](int st, int kt) {
        int k0 = kt * 32;
        for (int idx = tid; idx < 512; idx += NT) {
            int r = idx >> 2, c = (idx & 3) * 8;
            cpa16(Ah + st*ASTG + r*40 + c, Ab + (size_t)(m0 + r)*lda + k0 + c);
        }
        constexpr int CH = BN_ / 8;
        for (int idx = tid; idx < 32*CH; idx += NT) {
            int r = idx / CH, c = (idx % CH) * 8;
            cpa16(Bh + st*BSTG + r*BLD + c, Bb + (size_t)(k0 + r)*ldb + n0 + c);
        }
    };

    float acc[4][4][4] = {};
    const int KT = K >> 5;

    load_stage(0, 0); CP_COMMIT();
    if (KT > 1) { load_stage(1, 1); CP_COMMIT(); }
    if (KT > 1) asm volatile("cp.async.wait_group 1;\n" ::: "memory");
    else        asm volatile("cp.async.wait_group 0;\n" ::: "memory");
    __syncthreads();

    for (int c = 0; c < KT; c++) {
        int st = c % 3;
        const __half* a_s = Ah + st*ASTG;
        const __half* b_s = Bh + st*BSTG;

#pragma unroll
        for (int kk = 0; kk < 2; kk++) {
            int kc = kk*16 + ((lane >> 4) << 3);
            uint32_t af[4][4], bf[4][2];
#pragma unroll
            for (int mi = 0; mi < 4; mi++) {
                int ar = wm*64 + mi*16 + (lane & 15);
                ldsm4(af[mi][0], af[mi][1], af[mi][2], af[mi][3], a_s + ar*40 + kc);
            }
#pragma unroll
            for (int ng = 0; ng < 2; ng++) {
                uint32_t r0, r1, r2, r3;
                int rr = kk*16 + ((lane >> 4) << 3) + (lane & 7);
                int cc = wn*32 + ng*16 + (((lane >> 3) & 1) << 3);
                ldsm4t(r0, r1, r2, r3, b_s + rr*BLD + cc);
                bf[ng*2  ][0] = r0; bf[ng*2  ][1] = r2;
                bf[ng*2+1][0] = r1; bf[ng*2+1][1] = r3;
            }
#pragma unroll
            for (int mi = 0; mi < 4; mi++)
#pragma unroll
                for (int ni = 0; ni < 4; ni++) mma_f16(acc[mi][ni], af[mi], bf[ni]);
        }

        if (c + 2 < KT) {
            load_stage((c + 2) % 3, c + 2);
            CP_COMMIT();
            asm volatile("cp.async.wait_group 1;\n" ::: "memory");
            __syncthreads();
        } else if (c + 1 < KT) {
            asm volatile("cp.async.wait_group 0;\n" ::: "memory");
            __syncthreads();
        }
    }

    const float* biasb = (EPI <= 1) ? bias + z1*sBias1 + z2*sBias2 : nullptr;
#pragma unroll
    for (int mi = 0; mi < 4; mi++)
#pragma unroll
        for (int ni = 0; ni < 4; ni++) {
            int row = m0 + wm*64 + mi*16 + gid;
            int col = n0 + wn*32 + ni*8 + tig*2;
#pragma unroll
            for (int e2 = 0; e2 < 4; e2++) {
                int r  = row + (e2 >> 1)*8;
                int cc = col + (e2 & 1);
                float v = acc[mi][ni][e2];
                if (EPI == 0 || EPI == 1) v += biasb[cc];
                if (EPI == 1) v = fmaxf(v, 0.f);
                size_t idx = (size_t)(coff + (long long)r*ldc + cc);
                if (WMODE & 1) C[idx] = v;
                if (WMODE & 2) Ch[idx] = __float2half(v);
            }
        }
}

// ============ fused scores + mask + softmax (fp16 in/out) ===================
// Per (b,h): S = Q K^T / 8, (==0 -> NEGV), row softmax, write fp16 probs.
// CTA: 64 q-rows x full 512 k-cols, K=64 single shot. 256 thr, warps 2m x 4n.
__global__ void __launch_bounds__(256)
scores_softmax(const __half* __restrict__ qh, const __half* __restrict__ kh,
               __half* __restrict__ ph) {
    extern __shared__ __half sm[];
    __half* Qs = sm;                 // 64*72
    __half* Ks = Qs + 64*72;         // 512*72

    int bh = blockIdx.y, b = bh >> 3, h = bh & 7;
    int q0 = blockIdx.x * 64;
    int tid = threadIdx.x, lane = tid & 31, wid = tid >> 5;
    int wm = wid & 1, wn = wid >> 1;
    int gid = lane >> 2, tig = lane & 3;

    for (int idx = tid; idx < 512; idx += 256) {
        int r = idx >> 3, c = (idx & 7) * 8;
        cpa16(Qs + r*72 + c, qh + (size_t)(b*Sz + q0 + r)*Dm + h*DKh + c);
    }
    for (int idx = tid; idx < 4096; idx += 256) {
        int r = idx >> 3, c = (idx & 7) * 8;
        cpa16(Ks + r*72 + c, kh + (size_t)(b*Sz + r)*Dm + h*DKh + c);
    }
    CP_COMMIT();
    asm volatile("cp.async.wait_group 0;\n" ::: "memory");
    __syncthreads();

    float acc[2][16][4] = {};
#pragma unroll
    for (int kk = 0; kk < 4; kk++) {
        int kc = kk*16 + ((lane >> 4) << 3);
        uint32_t af[2][4];
#pragma unroll
        for (int mi = 0; mi < 2; mi++) {
            int ar = wm*32 + mi*16 + (lane & 15);
            ldsm4(af[mi][0], af[mi][1], af[mi][2], af[mi][3], Qs + ar*72 + kc);
        }
#pragma unroll
        for (int ng = 0; ng < 8; ng++) {
            int br = wn*128 + ng*16 + (lane & 15);
            uint32_t r0, r1, r2, r3;
            uint32_t bf[2][2];
            ldsm4(r0, r1, r2, r3, Ks + br*72 + kc);
            bf[0][0] = r0; bf[0][1] = r2; bf[1][0] = r1; bf[1][1] = r3;
#pragma unroll
            for (int mi = 0; mi < 2; mi++)
#pragma unroll
                for (int sub = 0; sub < 2; sub++)
                    mma_f16(acc[mi][ng*2+sub], af[mi], bf[sub]);
        }
    }
    __syncthreads();
    float* rmax = (float*)sm;        // [64][4]
    float* rsum = rmax + 256;        // [64][4]

#pragma unroll
    for (int mi = 0; mi < 2; mi++)
#pragma unroll
        for (int rh = 0; rh < 2; rh++) {
            float m1 = -INFINITY;
#pragma unroll
            for (int ni = 0; ni < 16; ni++)
#pragma unroll
                for (int nj = 0; nj < 2; nj++) {
                    float v = acc[mi][ni][rh*2+nj] * 0.125f;
                    if (v == 0.f) v = NEGV;
                    acc[mi][ni][rh*2+nj] = v;
                    m1 = fmaxf(m1, v);
                }
            m1 = fmaxf(m1, __shfl_xor_sync(0xffffffffu, m1, 1));
            m1 = fmaxf(m1, __shfl_xor_sync(0xffffffffu, m1, 2));
            int row = wm*32 + mi*16 + rh*8 + gid;
            if (tig == 0) rmax[row*4 + wn] = m1;
        }
    __syncthreads();
#pragma unroll
    for (int mi = 0; mi < 2; mi++)
#pragma unroll
        for (int rh = 0; rh < 2; rh++) {
            int row = wm*32 + mi*16 + rh*8 + gid;
            float mx = fmaxf(fmaxf(rmax[row*4+0], rmax[row*4+1]),
                             fmaxf(rmax[row*4+2], rmax[row*4+3]));
            float s1 = 0.f;
#pragma unroll
            for (int ni = 0; ni < 16; ni++)
#pragma unroll
                for (int nj = 0; nj < 2; nj++) {
                    float v = __expf(acc[mi][ni][rh*2+nj] - mx);
                    acc[mi][ni][rh*2+nj] = v;
                    s1 += v;
                }
            s1 += __shfl_xor_sync(0xffffffffu, s1, 1);
            s1 += __shfl_xor_sync(0xffffffffu, s1, 2);
            if (tig == 0) rsum[row*4 + wn] = s1;
        }
    __syncthreads();
#pragma unroll
    for (int mi = 0; mi < 2; mi++)
#pragma unroll
        for (int rh = 0; rh < 2; rh++) {
            int row = wm*32 + mi*16 + rh*8 + gid;
            float inv = 1.f / (rsum[row*4+0] + rsum[row*4+1] + rsum[row*4+2] + rsum[row*4+3]);
            size_t base = ((size_t)bh*Sz + q0 + row)*Sz;
#pragma unroll
            for (int ni = 0; ni < 16; ni++) {
                int col = wn*128 + (ni>>1)*16 + (ni&1)*8 + tig*2;
                __half2 hv = __floats2half2_rn(acc[mi][ni][rh*2+0] * inv,
                                               acc[mi][ni][rh*2+1] * inv);
                *(__half2*)(ph + base + col) = hv;
            }
        }
}

// ---------------- out = LayerNorm(a + res) (+ optional fp16 copy) -----------
template<int H16>
__global__ void add_ln(const float* __restrict__ a, const float* __restrict__ res,
                       const float* __restrict__ g, const float* __restrict__ beta,
                       float* __restrict__ out, __half* __restrict__ oh) {
    size_t row = blockIdx.x;
    int tid = threadIdx.x;
    int c = tid * 4;
    float4 av = *(const float4*)&a[row*Dm + c];
    float4 rv = *(const float4*)&res[row*Dm + c];
    float4 x;
    x.x = av.x + rv.x; x.y = av.y + rv.y; x.z = av.z + rv.z; x.w = av.w + rv.w;
    float s  = x.x + x.y + x.z + x.w;
    float s2 = x.x*x.x + x.y*x.y + x.z*x.z + x.w*x.w;
#pragma unroll
    for (int o = 16; o; o >>= 1) {
        s  += __shfl_xor_sync(0xffffffffu, s,  o);
        s2 += __shfl_xor_sync(0xffffffffu, s2, o);
    }
    __shared__ float sm[4], sq[4];
    if ((tid & 31) == 0) { sm[tid>>5] = s; sq[tid>>5] = s2; }
    __syncthreads();
    s  = sm[0] + sm[1] + sm[2] + sm[3];
    s2 = sq[0] + sq[1] + sq[2] + sq[3];
    float mean = s * (1.f/Dm);
    float var  = s2 * (1.f/Dm) - mean*mean;
    float inv  = rsqrtf(var + 1e-5f);
    float4 gv = *(const float4*)&g[c];
    float4 bv = *(const float4*)&beta[c];
    float y[4];
    y[0] = (x.x - mean)*inv*gv.x + bv.x;
    y[1] = (x.y - mean)*inv*gv.y + bv.y;
    y[2] = (x.z - mean)*inv*gv.z + bv.z;
    y[3] = (x.w - mean)*inv*gv.w + bv.w;
    *(float4*)&out[row*Dm + c] = *(float4*)y;
    if (H16) {
        __half2 h0 = __floats2half2_rn(y[0], y[1]);
        __half2 h1 = __floats2half2_rn(y[2], y[3]);
        *(__half2*)&oh[row*Dm + c]     = h0;
        *(__half2*)&oh[row*Dm + c + 2] = h1;
    }
}

// ---------------- decoder cross-attention (Sq=1, f32) ----------------
__global__ void cross_attn(const float* __restrict__ q, const float* __restrict__ k,
                           const float* __restrict__ v, float* __restrict__ o) {
    int h = blockIdx.x, b = blockIdx.y;
    __shared__ float qv[64];
    __shared__ float p[512];
    __shared__ float red[8];
    int tid = threadIdx.x;
    if (tid < 64) qv[tid] = q[b*Dm + h*DKh + tid];
    __syncthreads();
    float sc[2];
    float lmax = -INFINITY;
#pragma unroll
    for (int it = 0; it < 2; it++) {
        int j = tid + it*256;
        const float* kp = &k[(size_t)(b*Sz + j)*Dm + h*DKh];
        float s = 0.f;
#pragma unroll
        for (int c = 0; c < 64; c++) s += qv[c] * kp[c];
        s *= 0.125f;
        if (s == 0.f) s = NEGV;
        sc[it] = s;
        lmax = fmaxf(lmax, s);
    }
#pragma unroll
    for (int off = 16; off; off >>= 1) lmax = fmaxf(lmax, __shfl_xor_sync(0xffffffffu, lmax, off));
    if ((tid & 31) == 0) red[tid >> 5] = lmax;
    __syncthreads();
    float mx = red[0];
#pragma unroll
    for (int w = 1; w < 8; w++) mx = fmaxf(mx, red[w]);
    __syncthreads();
    float lsum = 0.f;
#pragma unroll
    for (int it = 0; it < 2; it++) {
        float e = __expf(sc[it] - mx);
        p[tid + it*256] = e;
        lsum += e;
    }
#pragma unroll
    for (int off = 16; off; off >>= 1) lsum += __shfl_xor_sync(0xffffffffu, lsum, off);
    if ((tid & 31) == 0) red[tid >> 5] = lsum;
    __syncthreads();
    float sum = red[0] + red[1] + red[2] + red[3] + red[4] + red[5] + red[6] + red[7];
    float inv = 1.f / sum;
    int warp = tid >> 5, lane = tid & 31;
#pragma unroll
    for (int dd = 0; dd < 8; dd++) {
        int d = warp*8 + dd;
        float acc = 0.f;
        for (int j = lane; j < Sz; j += 32)
            acc += p[j] * v[(size_t)(b*Sz + j)*Dm + h*DKh + d];
#pragma unroll
        for (int off = 16; off; off >>= 1) acc += __shfl_xor_sync(0xffffffffu, acc, off);
        if (lane == 0) o[b*Dm + h*DKh + d] = acc * inv;
    }
}

// ---------- tiny-M (M=8) GEMM, K-parallel: 512 thr = 64 cols x 8 K-slices ---
template<int RELU>
__global__ void __launch_bounds__(512)
gemm8w(const float* __restrict__ A, const float* __restrict__ W,
       const float* __restrict__ bias, float* __restrict__ C, int K, int N) {
    __shared__ float red[8][8][64];
    int t = threadIdx.x;
    int cl = t & 63;
    int col = blockIdx.x*64 + cl;
    int sl = t >> 6;
    float acc[8] = {};
    if (col < N) {
        int kn = K >> 3;
        int k0 = sl * kn, k1 = k0 + kn;
        for (int k = k0; k < k1; k++) {
            float wv = W[(size_t)k*N + col];
#pragma unroll
            for (int r = 0; r < 8; r++) acc[r] += A[r*K + k] * wv;
        }
    }
#pragma unroll
    for (int r = 0; r < 8; r++) red[r][sl][cl] = acc[r];
    __syncthreads();
    if (t < 64 && col < N) {
        float bv = bias[col];
#pragma unroll
        for (int r = 0; r < 8; r++) {
            float s = 0.f;
#pragma unroll
            for (int s8 = 0; s8 < 8; s8++) s += red[r][s8][t];
            float val = s + bv;
            if (RELU) val = fmaxf(val, 0.f);
            C[r*N + col] = val;
        }
    }
}

// ---------------- host orchestration ----------------
extern "C" void kernel_launch(void* const* d_in, const int* in_sizes, int n_in,
                              void* d_out, int out_size) {
    const int*   x        = (const int*)d_in[0];
    const int*   tgt      = (const int*)d_in[1];
    const float* in_emb   = (const float*)d_in[2];
    const float* out_emb  = (const float*)d_in[3];
    const float* enc_qkv_w = (const float*)d_in[4];
    const float* enc_qkv_b = (const float*)d_in[5];
    const float* enc_ln1_g = (const float*)d_in[6];
    const float* enc_ln1_b = (const float*)d_in[7];
    const float* enc_ffn1_w = (const float*)d_in[8];
    const float* enc_ffn1_b = (const float*)d_in[9];
    const float* enc_ffn2_w = (const float*)d_in[10];
    const float* enc_ffn2_b = (const float*)d_in[11];
    const float* enc_ln2_g = (const float*)d_in[12];
    const float* enc_ln2_b = (const float*)d_in[13];
    const float* dec_qkv1_w = (const float*)d_in[14];
    const float* dec_qkv1_b = (const float*)d_in[15];
    const float* dec_ln1_g = (const float*)d_in[16];
    const float* dec_ln1_b = (const float*)d_in[17];
    const float* dec_qkv2_w = (const float*)d_in[18];
    const float* dec_qkv2_b = (const float*)d_in[19];
    const float* dec_ln2_g = (const float*)d_in[20];
    const float* dec_ln2_b = (const float*)d_in[21];
    const float* dec_ffn1_w = (const float*)d_in[22];
    const float* dec_ffn1_b = (const float*)d_in[23];
    const float* dec_ffn2_w = (const float*)d_in[24];
    const float* dec_ffn2_b = (const float*)d_in[25];
    const float* dec_ln3_g = (const float*)d_in[26];
    const float* dec_ln3_b = (const float*)d_in[27];
    const float* out_w = (const float*)d_in[28];
    const float* out_b = (const float*)d_in[29];

    float *e, *attn, *tbuf, *dbuf, *dq, *dt, *dh, *kvf;
    __half *eh, *qkvh, *sch, *hh, *wqkvh, *wf1h, *wf2h, *wd2h;
    cudaGetSymbolAddress((void**)&e,    g_e);
    cudaGetSymbolAddress((void**)&eh,   g_eh);
    cudaGetSymbolAddress((void**)&qkvh, g_qkvh);
    cudaGetSymbolAddress((void**)&kvf,  g_kvf);
    cudaGetSymbolAddress((void**)&sch,  g_sch);
    cudaGetSymbolAddress((void**)&attn, g_attn);
    cudaGetSymbolAddress((void**)&hh,   g_hh);
    cudaGetSymbolAddress((void**)&tbuf, g_t);
    cudaGetSymbolAddress((void**)&dbuf, g_d);
    cudaGetSymbolAddress((void**)&dq,   g_dq);
    cudaGetSymbolAddress((void**)&dt,   g_dt);
    cudaGetSymbolAddress((void**)&dh,   g_dh);
    cudaGetSymbolAddress((void**)&wqkvh, g_wqkvh);
    cudaGetSymbolAddress((void**)&wf1h, g_wf1h);
    cudaGetSymbolAddress((void**)&wf2h, g_wf2h);
    cudaGetSymbolAddress((void**)&wd2h, g_wd2h);

    const int M = Bz*Sz;            // 4096
    const long long DD = (long long)Dm*Dm;
    const long long MD = (long long)M*Dm;
    const long long SS = (long long)Sz*Sz;
    const long long SDm = (long long)Sz*Dm;

    // smem (bytes): A = 3 stages * 128*40 * 2B = 30720
    const int SM_G128 = 30720 + 3*32*136*2;   // 56832
    const int SM_G64  = 30720 + 3*32*72*2;    // 44544
    const int SM_SC   = (64*72 + 512*72) * 2; // 82944
    cudaFuncSetAttribute(gemm_mma<128,0,2>, cudaFuncAttributeMaxDynamicSharedMemorySize, SM_G128);
    cudaFuncSetAttribute(gemm_mma<64,3,1>,  cudaFuncAttributeMaxDynamicSharedMemorySize, SM_G64);
    cudaFuncSetAttribute(gemm_mma<128,1,2>, cudaFuncAttributeMaxDynamicSharedMemorySize, SM_G128);
    cudaFuncSetAttribute(gemm_mma<128,0,1>, cudaFuncAttributeMaxDynamicSharedMemorySize, SM_G128);
    cudaFuncSetAttribute(scores_softmax,    cudaFuncAttributeMaxDynamicSharedMemorySize, SM_SC);

    // ---- convert weights once per launch ----
    {
        int n1 = Lz*3*Dm*Dm;
        convh<<<(n1+255)/256, 256>>>(enc_qkv_w, wqkvh, n1);
        int n2 = Lz*Dm*DFFz;
        convh<<<(n2+255)/256, 256>>>(enc_ffn1_w, wf1h, n2);
        convh<<<(n2+255)/256, 256>>>(enc_ffn2_w, wf2h, n2);
        convh<<<(n1+255)/256, 256>>>(dec_qkv2_w, wd2h, n1);
    }

    // ---------------- encoder ----------------
    embed_enc<<<(Bz*Sz*Dm + 255)/256, 256>>>(x, in_emb, e, eh);
    for (int i = 0; i < Lz; i++) {
        gemm_mma<128,0,2><<<dim3(Dm/128, M/128, 3), 256, SM_G128>>>(
            eh, wqkvh + (size_t)i*3*DD,
            enc_qkv_b + (size_t)i*3*Dm, nullptr, qkvh,
            Dm, Dm, Dm, Dm,
            1, 0, 0, DD, 0, MD, 0, Dm, 0);
        scores_softmax<<<dim3(Sz/64, Bz*Hn), 256, SM_SC>>>(
            qkvh, qkvh + MD, sch);
        gemm_mma<64,3,1><<<dim3(1, Sz/128, Bz*Hn), 128, SM_G64>>>(
            sch, qkvh + 2*MD, nullptr, attn, nullptr,
            Sz, Sz, Dm, Dm,
            Hn, (long long)Hn*SS, SS, SDm, DKh, SDm, DKh, 0, 0);
        add_ln<1><<<M, 128>>>(attn, e, enc_ln1_g + i*Dm, enc_ln1_b + i*Dm, e, eh);
        gemm_mma<128,1,2><<<dim3(DFFz/128, M/128, 1), 256, SM_G128>>>(
            eh, wf1h + (size_t)i*Dm*DFFz,
            enc_ffn1_b + (size_t)i*DFFz, nullptr, hh,
            Dm, Dm, DFFz, DFFz,
            1, 0, 0, 0, 0, 0, 0, 0, 0);
        gemm_mma<128,0,1><<<dim3(Dm/128, M/128, 1), 256, SM_G128>>>(
            hh, wf2h + (size_t)i*DFFz*Dm,
            enc_ffn2_b + (size_t)i*Dm, tbuf, nullptr,
            DFFz, DFFz, Dm, Dm,
            1, 0, 0, 0, 0, 0, 0, 0, 0);
        add_ln<1><<<M, 128>>>(tbuf, e, enc_ln2_g + i*Dm, enc_ln2_b + i*Dm, e, eh);
    }

    // ---- batched decoder cross K/V for ALL layers: z = Lz*2 = 12 ----
    gemm_mma<128,0,1><<<dim3(Dm/128, M/128, Lz*2), 256, SM_G128>>>(
        eh, wd2h + DD,
        dec_qkv2_b + Dm, kvf, nullptr,
        Dm, Dm, Dm, Dm,
        2, 0, 0, 3*DD, DD, 2*MD, MD, 3*(long long)Dm, Dm);

    // ---------------- decoder (seq len 1; self-attn == V projection) --------
    embed_dec<<<(Bz*Dm + 255)/256, 256>>>(tgt, out_emb, dbuf);
    for (int i = 0; i < Lz; i++) {
        gemm8w<0><<<Dm/64, 512>>>(dbuf, dec_qkv1_w + (size_t)(i*3+2)*DD, dec_qkv1_b + (i*3+2)*Dm, dt, Dm, Dm);
        add_ln<0><<<Bz, 128>>>(dt, dbuf, dec_ln1_g + i*Dm, dec_ln1_b + i*Dm, dbuf, nullptr);
        gemm8w<0><<<Dm/64, 512>>>(dbuf, dec_qkv2_w + (size_t)(i*3+0)*DD, dec_qkv2_b + (i*3+0)*Dm, dq, Dm, Dm);
        cross_attn<<<dim3(Hn, Bz), 256>>>(dq, kvf + (size_t)i*2*MD, kvf + (size_t)i*2*MD + MD, dt);
        add_ln<0><<<Bz, 128>>>(dt, dbuf, dec_ln2_g + i*Dm, dec_ln2_b + i*Dm, dbuf, nullptr);
        gemm8w<1><<<DFFz/64, 512>>>(dbuf, dec_ffn1_w + (size_t)i*Dm*DFFz, dec_ffn1_b + i*DFFz, dh, Dm, DFFz);
        gemm8w<0><<<Dm/64, 512>>>(dh, dec_ffn2_w + (size_t)i*DFFz*Dm, dec_ffn2_b + i*Dm, dt, DFFz, Dm);
        add_ln<0><<<Bz, 128>>>(dt, dbuf, dec_ln3_g + i*Dm, dec_ln3_b + i*Dm, dbuf, nullptr);
    }

    // output projection -> d_out [8,1,1000]
    gemm8w<0><<<(OUTz+63)/64, 512>>>(dbuf, out_w, out_b, (float*)d_out, Dm, OUTz);
    (void)in_sizes; (void)n_in; (void)out_size;
}

// round 11
// speedup vs baseline: 3.5898x; 1.0351x over previous
#include <cuda_runtime.h>
#include <cuda_fp16.h>
#include <math.h>
#include <stdint.h>

#define Bz   8
#define Sz   512
#define Dm   512
#define Hn   8
#define DKh  64
#define Lz   6
#define DFFz 2048
#define OUTz 1000
#define NEGV (-1e9f)

// ---------------- scratch (device globals) ----------------
__device__ float g_e[Bz*Sz*Dm];
__device__ __half g_eh[Bz*Sz*Dm];
__device__ __half g_qkvh[3*Bz*Sz*Dm];
__device__ float g_kvf[(size_t)Lz*2*Bz*Sz*Dm];
__device__ float g_attn[Bz*Sz*Dm];
__device__ __half g_hh[Bz*Sz*DFFz];
__device__ float g_t[Bz*Sz*Dm];
__device__ float g_d[Bz*Dm];
__device__ float g_dq[Bz*Dm];
__device__ float g_dt[Bz*Dm];
__device__ float g_dh[Bz*DFFz];
// fp16 weights in original [K,N] layout
__device__ __half g_wqkvh[Lz*3*Dm*Dm];
__device__ __half g_wf1h[Lz*Dm*DFFz];
__device__ __half g_wf2h[Lz*DFFz*Dm];
__device__ __half g_wd2h[Lz*3*Dm*Dm];

// ---------------- helpers ----------------
__device__ __forceinline__ void cpa16(void* dst, const void* src) {
    uint32_t d = (uint32_t)__cvta_generic_to_shared(dst);
    asm volatile("cp.async.ca.shared.global [%0], [%1], 16;\n" :: "r"(d), "l"(src));
}
#define CP_COMMIT() asm volatile("cp.async.commit_group;\n" ::: "memory")
__device__ __forceinline__ void ldsm4(uint32_t& r0, uint32_t& r1, uint32_t& r2, uint32_t& r3,
                                      const void* p) {
    uint32_t a = (uint32_t)__cvta_generic_to_shared(p);
    asm volatile("ldmatrix.sync.aligned.m8n8.x4.shared.b16 {%0,%1,%2,%3}, [%4];\n"
                 : "=r"(r0), "=r"(r1), "=r"(r2), "=r"(r3) : "r"(a));
}
__device__ __forceinline__ void ldsm4t(uint32_t& r0, uint32_t& r1, uint32_t& r2, uint32_t& r3,
                                       const void* p) {
    uint32_t a = (uint32_t)__cvta_generic_to_shared(p);
    asm volatile("ldmatrix.sync.aligned.m8n8.x4.trans.shared.b16 {%0,%1,%2,%3}, [%4];\n"
                 : "=r"(r0), "=r"(r1), "=r"(r2), "=r"(r3) : "r"(a));
}
__device__ __forceinline__ void mma_f16(float c[4], const uint32_t a[4], const uint32_t b[2]) {
    asm volatile(
        "mma.sync.aligned.m16n8k16.row.col.f32.f16.f16.f32 "
        "{%0,%1,%2,%3}, {%4,%5,%6,%7}, {%8,%9}, {%0,%1,%2,%3};\n"
        : "+f"(c[0]), "+f"(c[1]), "+f"(c[2]), "+f"(c[3])
        : "r"(a[0]), "r"(a[1]), "r"(a[2]), "r"(a[3]), "r"(b[0]), "r"(b[1]));
}

// ---------------- convert 4 weight arrays f32 -> fp16 in one launch ---------
__global__ void convh_all(const float* __restrict__ s0, __half* __restrict__ d0, int n0,
                          const float* __restrict__ s1, __half* __restrict__ d1, int n1,
                          const float* __restrict__ s2, __half* __restrict__ d2, int n2,
                          const float* __restrict__ s3, __half* __restrict__ d3, int n3) {
    int i = blockIdx.x*blockDim.x + threadIdx.x;
    if (i < n0) { d0[i] = __float2half(s0[i]); return; }
    i -= n0;
    if (i < n1) { d1[i] = __float2half(s1[i]); return; }
    i -= n1;
    if (i < n2) { d2[i] = __float2half(s2[i]); return; }
    i -= n2;
    if (i < n3) { d3[i] = __float2half(s3[i]); }
}

// ---------------- embedding + PE ----------------
__global__ void embed_enc(const int* __restrict__ x, const float* __restrict__ emb,
                          float* __restrict__ e, __half* __restrict__ eh) {
    int idx = blockIdx.x*blockDim.x + threadIdx.x;
    if (idx >= Bz*Sz*Dm) return;
    int d  = idx % Dm;
    int bs = idx / Dm;
    int s  = bs % Sz;
    int tok = x[bs];
    float div = exp2f(-(float)(d & ~1) * (13.287712379549449f / (float)Dm));
    float arg = (float)s * div;
    float pe = (d & 1) ? cosf(arg) : sinf(arg);
    float v = emb[tok*Dm + d] * 22.627416997969522f + pe;
    e[idx] = v;
    eh[idx] = __float2half(v);
}

__global__ void embed_dec(const int* __restrict__ tgt, const float* __restrict__ emb,
                          float* __restrict__ o) {
    int idx = blockIdx.x*blockDim.x + threadIdx.x;
    if (idx >= Bz*Dm) return;
    int d = idx % Dm;
    int b = idx / Dm;
    float pe = (d & 1) ? 1.f : 0.f;
    o[idx] = emb[tgt[b]*Dm + d] * 22.627416997969522f + pe;
}

// ============ 3-stage pipelined mma.sync GEMM (fp16, big tiles) =============
template<int BN_, int EPI, int WMODE>
__global__ void __launch_bounds__(BN_ == 128 ? 256 : 128)
gemm_mma(const __half* __restrict__ Ag, const __half* __restrict__ Bg,
         const float* __restrict__ bias,
         float* __restrict__ C, __half* __restrict__ Ch,
         int K, int lda, int ldb, int ldc,
         int zdiv, long long sA1, long long sA2, long long sB1, long long sB2,
         long long sC1, long long sC2, long long sBias1, long long sBias2) {
    constexpr int NT   = (BN_ == 128) ? 256 : 128;
    constexpr int ASTG = 128 * 40;
    constexpr int BLD  = BN_ + 8;
    constexpr int BSTG = 32 * BLD;

    extern __shared__ __half sm[];
    __half* Ah = sm;
    __half* Bh = Ah + 3*ASTG;

    int z = blockIdx.z, z1 = z / zdiv, z2 = z % zdiv;
    const __half* Ab = Ag + z1*sA1 + z2*sA2;
    const __half* Bb = Bg + z1*sB1 + z2*sB2;
    long long coff = z1*sC1 + z2*sC2;

    int m0 = blockIdx.y * 128, n0 = blockIdx.x * BN_;
    int tid = threadIdx.x, lane = tid & 31, wid = tid >> 5;
    int wm = wid & 1, wn = wid >> 1;
    int gid = lane >> 2, tig = lane & 3;

    auto load_stage = [&](int st, int kt) {
        int k0 = kt * 32;
        for (int idx = tid; idx < 512; idx += NT) {
            int r = idx >> 2, c = (idx & 3) * 8;
            cpa16(Ah + st*ASTG + r*40 + c, Ab + (size_t)(m0 + r)*lda + k0 + c);
        }
        constexpr int CH = BN_ / 8;
        for (int idx = tid; idx < 32*CH; idx += NT) {
            int r = idx / CH, c = (idx % CH) * 8;
            cpa16(Bh + st*BSTG + r*BLD + c, Bb + (size_t)(k0 + r)*ldb + n0 + c);
        }
    };

    float acc[4][4][4] = {};
    const int KT = K >> 5;

    load_stage(0, 0); CP_COMMIT();
    if (KT > 1) { load_stage(1, 1); CP_COMMIT(); }
    if (KT > 1) asm volatile("cp.async.wait_group 1;\n" ::: "memory");
    else        asm volatile("cp.async.wait_group 0;\n" ::: "memory");
    __syncthreads();

    for (int c = 0; c < KT; c++) {
        int st = c % 3;
        const __half* a_s = Ah + st*ASTG;
        const __half* b_s = Bh + st*BSTG;

#pragma unroll
        for (int kk = 0; kk < 2; kk++) {
            int kc = kk*16 + ((lane >> 4) << 3);
            uint32_t af[4][4], bf[4][2];
#pragma unroll
            for (int mi = 0; mi < 4; mi++) {
                int ar = wm*64 + mi*16 + (lane & 15);
                ldsm4(af[mi][0], af[mi][1], af[mi][2], af[mi][3], a_s + ar*40 + kc);
            }
#pragma unroll
            for (int ng = 0; ng < 2; ng++) {
                uint32_t r0, r1, r2, r3;
                int rr = kk*16 + ((lane >> 4) << 3) + (lane & 7);
                int cc = wn*32 + ng*16 + (((lane >> 3) & 1) << 3);
                ldsm4t(r0, r1, r2, r3, b_s + rr*BLD + cc);
                bf[ng*2  ][0] = r0; bf[ng*2  ][1] = r2;
                bf[ng*2+1][0] = r1; bf[ng*2+1][1] = r3;
            }
#pragma unroll
            for (int mi = 0; mi < 4; mi++)
#pragma unroll
                for (int ni = 0; ni < 4; ni++) mma_f16(acc[mi][ni], af[mi], bf[ni]);
        }

        if (c + 2 < KT) {
            load_stage((c + 2) % 3, c + 2);
            CP_COMMIT();
            asm volatile("cp.async.wait_group 1;\n" ::: "memory");
            __syncthreads();
        } else if (c + 1 < KT) {
            asm volatile("cp.async.wait_group 0;\n" ::: "memory");
            __syncthreads();
        }
    }

    const float* biasb = (EPI <= 1) ? bias + z1*sBias1 + z2*sBias2 : nullptr;
#pragma unroll
    for (int mi = 0; mi < 4; mi++)
#pragma unroll
        for (int ni = 0; ni < 4; ni++) {
            int row = m0 + wm*64 + mi*16 + gid;
            int col = n0 + wn*32 + ni*8 + tig*2;
#pragma unroll
            for (int e2 = 0; e2 < 4; e2++) {
                int r  = row + (e2 >> 1)*8;
                int cc = col + (e2 & 1);
                float v = acc[mi][ni][e2];
                if (EPI == 0 || EPI == 1) v += biasb[cc];
                if (EPI == 1) v = fmaxf(v, 0.f);
                size_t idx = (size_t)(coff + (long long)r*ldc + cc);
                if (WMODE & 1) C[idx] = v;
                if (WMODE & 2) Ch[idx] = __float2half(v);
            }
        }
}

// ============ fused attention: S=QK^T/8 + mask + softmax + O=PV =============
// Per (q-tile 64, bh): full k-len 512 in one CTA. 256 thr, 8 warps.
// Phase 1: warps 2m x 4n compute S (acc in regs), softmax in regs.
// Phase 2: P -> smem fp16, V cp.async (overlapped), warps 2m x 4n (16-col) PV.
__global__ void __launch_bounds__(256)
attn_fused(const __half* __restrict__ qh, const __half* __restrict__ kh,
           const __half* __restrict__ vh, float* __restrict__ attn) {
    extern __shared__ __half sm[];
    __half* Qs = sm;                        // [64][72]
    __half* Ks = sm + 64*72;                // [512][72]
    __half* Ps = sm;                        // [64][520]  (phase 2, overlays Qs/Ks)
    __half* Vs = sm + 64*520;               // [512][72]  (phase 2)
    float* rmax = (float*)(sm + 70144);     // [64][4]
    float* rsum = rmax + 256;               // [64][4]

    int bh = blockIdx.y, b = bh >> 3, h = bh & 7;
    int q0 = blockIdx.x * 64;
    int tid = threadIdx.x, lane = tid & 31, wid = tid >> 5;
    int wm = wid & 1, wn = wid >> 1;
    int gid = lane >> 2, tig = lane & 3;

    for (int idx = tid; idx < 512; idx += 256) {
        int r = idx >> 3, c = (idx & 7) * 8;
        cpa16(Qs + r*72 + c, qh + (size_t)(b*Sz + q0 + r)*Dm + h*DKh + c);
    }
    for (int idx = tid; idx < 4096; idx += 256) {
        int r = idx >> 3, c = (idx & 7) * 8;
        cpa16(Ks + r*72 + c, kh + (size_t)(b*Sz + r)*Dm + h*DKh + c);
    }
    CP_COMMIT();
    asm volatile("cp.async.wait_group 0;\n" ::: "memory");
    __syncthreads();

    // ---- phase 1: S = Q K^T ----
    float acc[2][16][4] = {};
#pragma unroll
    for (int kk = 0; kk < 4; kk++) {
        int kc = kk*16 + ((lane >> 4) << 3);
        uint32_t af[2][4];
#pragma unroll
        for (int mi = 0; mi < 2; mi++) {
            int ar = wm*32 + mi*16 + (lane & 15);
            ldsm4(af[mi][0], af[mi][1], af[mi][2], af[mi][3], Qs + ar*72 + kc);
        }
#pragma unroll
        for (int ng = 0; ng < 8; ng++) {
            int br = wn*128 + ng*16 + (lane & 15);
            uint32_t r0, r1, r2, r3;
            uint32_t bf[2][2];
            ldsm4(r0, r1, r2, r3, Ks + br*72 + kc);
            bf[0][0] = r0; bf[0][1] = r2; bf[1][0] = r1; bf[1][1] = r3;
#pragma unroll
            for (int mi = 0; mi < 2; mi++)
#pragma unroll
                for (int sub = 0; sub < 2; sub++)
                    mma_f16(acc[mi][ng*2+sub], af[mi], bf[sub]);
        }
    }
    __syncthreads();          // Qs/Ks dead; safe to overlay

    // ---- start V loads (overlap with softmax) ----
    for (int idx = tid; idx < 4096; idx += 256) {
        int r = idx >> 3, c = (idx & 7) * 8;
        cpa16(Vs + r*72 + c, vh + (size_t)(b*Sz + r)*Dm + h*DKh + c);
    }
    CP_COMMIT();

    // ---- softmax over regs ----
#pragma unroll
    for (int mi = 0; mi < 2; mi++)
#pragma unroll
        for (int rh = 0; rh < 2; rh++) {
            float m1 = -INFINITY;
#pragma unroll
            for (int ni = 0; ni < 16; ni++)
#pragma unroll
                for (int nj = 0; nj < 2; nj++) {
                    float v = acc[mi][ni][rh*2+nj] * 0.125f;
                    if (v == 0.f) v = NEGV;
                    acc[mi][ni][rh*2+nj] = v;
                    m1 = fmaxf(m1, v);
                }
            m1 = fmaxf(m1, __shfl_xor_sync(0xffffffffu, m1, 1));
            m1 = fmaxf(m1, __shfl_xor_sync(0xffffffffu, m1, 2));
            int row = wm*32 + mi*16 + rh*8 + gid;
            if (tig == 0) rmax[row*4 + wn] = m1;
        }
    __syncthreads();
#pragma unroll
    for (int mi = 0; mi < 2; mi++)
#pragma unroll
        for (int rh = 0; rh < 2; rh++) {
            int row = wm*32 + mi*16 + rh*8 + gid;
            float mx = fmaxf(fmaxf(rmax[row*4+0], rmax[row*4+1]),
                             fmaxf(rmax[row*4+2], rmax[row*4+3]));
            float s1 = 0.f;
#pragma unroll
            for (int ni = 0; ni < 16; ni++)
#pragma unroll
                for (int nj = 0; nj < 2; nj++) {
                    float v = __expf(acc[mi][ni][rh*2+nj] - mx);
                    acc[mi][ni][rh*2+nj] = v;
                    s1 += v;
                }
            s1 += __shfl_xor_sync(0xffffffffu, s1, 1);
            s1 += __shfl_xor_sync(0xffffffffu, s1, 2);
            if (tig == 0) rsum[row*4 + wn] = s1;
        }
    __syncthreads();
    // ---- write P (fp16) into smem ----
#pragma unroll
    for (int mi = 0; mi < 2; mi++)
#pragma unroll
        for (int rh = 0; rh < 2; rh++) {
            int row = wm*32 + mi*16 + rh*8 + gid;
            float inv = 1.f / (rsum[row*4+0] + rsum[row*4+1] + rsum[row*4+2] + rsum[row*4+3]);
#pragma unroll
            for (int ni = 0; ni < 16; ni++) {
                int col = wn*128 + (ni>>1)*16 + (ni&1)*8 + tig*2;
                __half2 hv = __floats2half2_rn(acc[mi][ni][rh*2+0] * inv,
                                               acc[mi][ni][rh*2+1] * inv);
                *(__half2*)(Ps + row*520 + col) = hv;
            }
        }
    asm volatile("cp.async.wait_group 0;\n" ::: "memory");
    __syncthreads();

    // ---- phase 2: O = P V  (warp tile 32 rows x 16 cols) ----
    float o[2][2][4] = {};
#pragma unroll 4
    for (int kk = 0; kk < 32; kk++) {
        int kc = kk*16 + ((lane >> 4) << 3);
        uint32_t af[2][4];
#pragma unroll
        for (int mi = 0; mi < 2; mi++) {
            int ar = wm*32 + mi*16 + (lane & 15);
            ldsm4(af[mi][0], af[mi][1], af[mi][2], af[mi][3], Ps + ar*520 + kc);
        }
        uint32_t r0, r1, r2, r3;
        int rr = kk*16 + ((lane >> 4) << 3) + (lane & 7);
        int cc = wn*16 + (((lane >> 3) & 1) << 3);
        ldsm4t(r0, r1, r2, r3, Vs + rr*72 + cc);
        uint32_t bf[2][2];
        bf[0][0] = r0; bf[0][1] = r2; bf[1][0] = r1; bf[1][1] = r3;
#pragma unroll
        for (int mi = 0; mi < 2; mi++)
#pragma unroll
            for (int n8 = 0; n8 < 2; n8++)
                mma_f16(o[mi][n8], af[mi], bf[n8]);
    }

    // ---- epilogue: write attn f32 ----
#pragma unroll
    for (int mi = 0; mi < 2; mi++)
#pragma unroll
        for (int n8 = 0; n8 < 2; n8++) {
            int row = q0 + wm*32 + mi*16 + gid;
            int col = h*DKh + wn*16 + n8*8 + tig*2;
#pragma unroll
            for (int e2 = 0; e2 < 4; e2++) {
                int r  = row + (e2 >> 1)*8;
                int cc = col + (e2 & 1);
                attn[(size_t)(b*Sz + r)*Dm + cc] = o[mi][n8][e2];
            }
        }
}

// ---------------- out = LayerNorm(a + res) (+ optional fp16 copy) -----------
template<int H16>
__global__ void add_ln(const float* __restrict__ a, const float* __restrict__ res,
                       const float* __restrict__ g, const float* __restrict__ beta,
                       float* __restrict__ out, __half* __restrict__ oh) {
    size_t row = blockIdx.x;
    int tid = threadIdx.x;
    int c = tid * 4;
    float4 av = *(const float4*)&a[row*Dm + c];
    float4 rv = *(const float4*)&res[row*Dm + c];
    float4 x;
    x.x = av.x + rv.x; x.y = av.y + rv.y; x.z = av.z + rv.z; x.w = av.w + rv.w;
    float s  = x.x + x.y + x.z + x.w;
    float s2 = x.x*x.x + x.y*x.y + x.z*x.z + x.w*x.w;
#pragma unroll
    for (int o = 16; o; o >>= 1) {
        s  += __shfl_xor_sync(0xffffffffu, s,  o);
        s2 += __shfl_xor_sync(0xffffffffu, s2, o);
    }
    __shared__ float sm[4], sq[4];
    if ((tid & 31) == 0) { sm[tid>>5] = s; sq[tid>>5] = s2; }
    __syncthreads();
    s  = sm[0] + sm[1] + sm[2] + sm[3];
    s2 = sq[0] + sq[1] + sq[2] + sq[3];
    float mean = s * (1.f/Dm);
    float var  = s2 * (1.f/Dm) - mean*mean;
    float inv  = rsqrtf(var + 1e-5f);
    float4 gv = *(const float4*)&g[c];
    float4 bv = *(const float4*)&beta[c];
    float y[4];
    y[0] = (x.x - mean)*inv*gv.x + bv.x;
    y[1] = (x.y - mean)*inv*gv.y + bv.y;
    y[2] = (x.z - mean)*inv*gv.z + bv.z;
    y[3] = (x.w - mean)*inv*gv.w + bv.w;
    *(float4*)&out[row*Dm + c] = *(float4*)y;
    if (H16) {
        __half2 h0 = __floats2half2_rn(y[0], y[1]);
        __half2 h1 = __floats2half2_rn(y[2], y[3]);
        *(__half2*)&oh[row*Dm + c]     = h0;
        *(__half2*)&oh[row*Dm + c + 2] = h1;
    }
}

// ---------------- decoder cross-attention (Sq=1, f32) ----------------
__global__ void cross_attn(const float* __restrict__ q, const float* __restrict__ k,
                           const float* __restrict__ v, float* __restrict__ o) {
    int h = blockIdx.x, b = blockIdx.y;
    __shared__ float qv[64];
    __shared__ float p[512];
    __shared__ float red[8];
    int tid = threadIdx.x;
    if (tid < 64) qv[tid] = q[b*Dm + h*DKh + tid];
    __syncthreads();
    float sc[2];
    float lmax = -INFINITY;
#pragma unroll
    for (int it = 0; it < 2; it++) {
        int j = tid + it*256;
        const float* kp = &k[(size_t)(b*Sz + j)*Dm + h*DKh];
        float s = 0.f;
#pragma unroll
        for (int c = 0; c < 64; c++) s += qv[c] * kp[c];
        s *= 0.125f;
        if (s == 0.f) s = NEGV;
        sc[it] = s;
        lmax = fmaxf(lmax, s);
    }
#pragma unroll
    for (int off = 16; off; off >>= 1) lmax = fmaxf(lmax, __shfl_xor_sync(0xffffffffu, lmax, off));
    if ((tid & 31) == 0) red[tid >> 5] = lmax;
    __syncthreads();
    float mx = red[0];
#pragma unroll
    for (int w = 1; w < 8; w++) mx = fmaxf(mx, red[w]);
    __syncthreads();
    float lsum = 0.f;
#pragma unroll
    for (int it = 0; it < 2; it++) {
        float e = __expf(sc[it] - mx);
        p[tid + it*256] = e;
        lsum += e;
    }
#pragma unroll
    for (int off = 16; off; off >>= 1) lsum += __shfl_xor_sync(0xffffffffu, lsum, off);
    if ((tid & 31) == 0) red[tid >> 5] = lsum;
    __syncthreads();
    float sum = red[0] + red[1] + red[2] + red[3] + red[4] + red[5] + red[6] + red[7];
    float inv = 1.f / sum;
    int warp = tid >> 5, lane = tid & 31;
#pragma unroll
    for (int dd = 0; dd < 8; dd++) {
        int d = warp*8 + dd;
        float acc = 0.f;
        for (int j = lane; j < Sz; j += 32)
            acc += p[j] * v[(size_t)(b*Sz + j)*Dm + h*DKh + d];
#pragma unroll
        for (int off = 16; off; off >>= 1) acc += __shfl_xor_sync(0xffffffffu, acc, off);
        if (lane == 0) o[b*Dm + h*DKh + d] = acc * inv;
    }
}

// ---------- tiny-M (M=8) GEMM, K-parallel: 512 thr = 64 cols x 8 K-slices ---
template<int RELU>
__global__ void __launch_bounds__(512)
gemm8w(const float* __restrict__ A, const float* __restrict__ W,
       const float* __restrict__ bias, float* __restrict__ C, int K, int N) {
    __shared__ float red[8][8][64];
    int t = threadIdx.x;
    int cl = t & 63;
    int col = blockIdx.x*64 + cl;
    int sl = t >> 6;
    float acc[8] = {};
    if (col < N) {
        int kn = K >> 3;
        int k0 = sl * kn, k1 = k0 + kn;
        for (int k = k0; k < k1; k++) {
            float wv = W[(size_t)k*N + col];
#pragma unroll
            for (int r = 0; r < 8; r++) acc[r] += A[r*K + k] * wv;
        }
    }
#pragma unroll
    for (int r = 0; r < 8; r++) red[r][sl][cl] = acc[r];
    __syncthreads();
    if (t < 64 && col < N) {
        float bv = bias[col];
#pragma unroll
        for (int r = 0; r < 8; r++) {
            float s = 0.f;
#pragma unroll
            for (int s8 = 0; s8 < 8; s8++) s += red[r][s8][t];
            float val = s + bv;
            if (RELU) val = fmaxf(val, 0.f);
            C[r*N + col] = val;
        }
    }
}

// ---------------- host orchestration ----------------
extern "C" void kernel_launch(void* const* d_in, const int* in_sizes, int n_in,
                              void* d_out, int out_size) {
    const int*   x        = (const int*)d_in[0];
    const int*   tgt      = (const int*)d_in[1];
    const float* in_emb   = (const float*)d_in[2];
    const float* out_emb  = (const float*)d_in[3];
    const float* enc_qkv_w = (const float*)d_in[4];
    const float* enc_qkv_b = (const float*)d_in[5];
    const float* enc_ln1_g = (const float*)d_in[6];
    const float* enc_ln1_b = (const float*)d_in[7];
    const float* enc_ffn1_w = (const float*)d_in[8];
    const float* enc_ffn1_b = (const float*)d_in[9];
    const float* enc_ffn2_w = (const float*)d_in[10];
    const float* enc_ffn2_b = (const float*)d_in[11];
    const float* enc_ln2_g = (const float*)d_in[12];
    const float* enc_ln2_b = (const float*)d_in[13];
    const float* dec_qkv1_w = (const float*)d_in[14];
    const float* dec_qkv1_b = (const float*)d_in[15];
    const float* dec_ln1_g = (const float*)d_in[16];
    const float* dec_ln1_b = (const float*)d_in[17];
    const float* dec_qkv2_w = (const float*)d_in[18];
    const float* dec_qkv2_b = (const float*)d_in[19];
    const float* dec_ln2_g = (const float*)d_in[20];
    const float* dec_ln2_b = (const float*)d_in[21];
    const float* dec_ffn1_w = (const float*)d_in[22];
    const float* dec_ffn1_b = (const float*)d_in[23];
    const float* dec_ffn2_w = (const float*)d_in[24];
    const float* dec_ffn2_b = (const float*)d_in[25];
    const float* dec_ln3_g = (const float*)d_in[26];
    const float* dec_ln3_b = (const float*)d_in[27];
    const float* out_w = (const float*)d_in[28];
    const float* out_b = (const float*)d_in[29];

    float *e, *attn, *tbuf, *dbuf, *dq, *dt, *dh, *kvf;
    __half *eh, *qkvh, *hh, *wqkvh, *wf1h, *wf2h, *wd2h;
    cudaGetSymbolAddress((void**)&e,    g_e);
    cudaGetSymbolAddress((void**)&eh,   g_eh);
    cudaGetSymbolAddress((void**)&qkvh, g_qkvh);
    cudaGetSymbolAddress((void**)&kvf,  g_kvf);
    cudaGetSymbolAddress((void**)&attn, g_attn);
    cudaGetSymbolAddress((void**)&hh,   g_hh);
    cudaGetSymbolAddress((void**)&tbuf, g_t);
    cudaGetSymbolAddress((void**)&dbuf, g_d);
    cudaGetSymbolAddress((void**)&dq,   g_dq);
    cudaGetSymbolAddress((void**)&dt,   g_dt);
    cudaGetSymbolAddress((void**)&dh,   g_dh);
    cudaGetSymbolAddress((void**)&wqkvh, g_wqkvh);
    cudaGetSymbolAddress((void**)&wf1h, g_wf1h);
    cudaGetSymbolAddress((void**)&wf2h, g_wf2h);
    cudaGetSymbolAddress((void**)&wd2h, g_wd2h);

    const int M = Bz*Sz;            // 4096
    const long long DD = (long long)Dm*Dm;
    const long long MD = (long long)M*Dm;

    const int SM_G128 = 30720 + 3*32*136*2;   // 56832
    const int SM_AT   = 70144*2 + 2048;       // 142336
    cudaFuncSetAttribute(gemm_mma<128,0,2>, cudaFuncAttributeMaxDynamicSharedMemorySize, SM_G128);
    cudaFuncSetAttribute(gemm_mma<128,1,2>, cudaFuncAttributeMaxDynamicSharedMemorySize, SM_G128);
    cudaFuncSetAttribute(gemm_mma<128,0,1>, cudaFuncAttributeMaxDynamicSharedMemorySize, SM_G128);
    cudaFuncSetAttribute(attn_fused,        cudaFuncAttributeMaxDynamicSharedMemorySize, SM_AT);

    // ---- convert all weights once, in a single launch ----
    {
        int n1 = Lz*3*Dm*Dm;      // 4.7M
        int n2 = Lz*Dm*DFFz;      // 6.3M
        long long total = 2LL*n1 + 2LL*n2;
        convh_all<<<(int)((total + 255)/256), 256>>>(
            enc_qkv_w, wqkvh, n1,
            enc_ffn1_w, wf1h, n2,
            enc_ffn2_w, wf2h, n2,
            dec_qkv2_w, wd2h, n1);
    }

    // ---------------- encoder ----------------
    embed_enc<<<(Bz*Sz*Dm + 255)/256, 256>>>(x, in_emb, e, eh);
    for (int i = 0; i < Lz; i++) {
        gemm_mma<128,0,2><<<dim3(Dm/128, M/128, 3), 256, SM_G128>>>(
            eh, wqkvh + (size_t)i*3*DD,
            enc_qkv_b + (size_t)i*3*Dm, nullptr, qkvh,
            Dm, Dm, Dm, Dm,
            1, 0, 0, DD, 0, MD, 0, Dm, 0);
        attn_fused<<<dim3(Sz/64, Bz*Hn), 256, SM_AT>>>(
            qkvh, qkvh + MD, qkvh + 2*MD, attn);
        add_ln<1><<<M, 128>>>(attn, e, enc_ln1_g + i*Dm, enc_ln1_b + i*Dm, e, eh);
        gemm_mma<128,1,2><<<dim3(DFFz/128, M/128, 1), 256, SM_G128>>>(
            eh, wf1h + (size_t)i*Dm*DFFz,
            enc_ffn1_b + (size_t)i*DFFz, nullptr, hh,
            Dm, Dm, DFFz, DFFz,
            1, 0, 0, 0, 0, 0, 0, 0, 0);
        gemm_mma<128,0,1><<<dim3(Dm/128, M/128, 1), 256, SM_G128>>>(
            hh, wf2h + (size_t)i*DFFz*Dm,
            enc_ffn2_b + (size_t)i*Dm, tbuf, nullptr,
            DFFz, DFFz, Dm, Dm,
            1, 0, 0, 0, 0, 0, 0, 0, 0);
        add_ln<1><<<M, 128>>>(tbuf, e, enc_ln2_g + i*Dm, enc_ln2_b + i*Dm, e, eh);
    }

    // ---- batched decoder cross K/V for ALL layers: z = Lz*2 = 12 ----
    gemm_mma<128,0,1><<<dim3(Dm/128, M/128, Lz*2), 256, SM_G128>>>(
        eh, wd2h + DD,
        dec_qkv2_b + Dm, kvf, nullptr,
        Dm, Dm, Dm, Dm,
        2, 0, 0, 3*DD, DD, 2*MD, MD, 3*(long long)Dm, Dm);

    // ---------------- decoder (seq len 1; self-attn == V projection) --------
    embed_dec<<<(Bz*Dm + 255)/256, 256>>>(tgt, out_emb, dbuf);
    for (int i = 0; i < Lz; i++) {
        gemm8w<0><<<Dm/64, 512>>>(dbuf, dec_qkv1_w + (size_t)(i*3+2)*DD, dec_qkv1_b + (i*3+2)*Dm, dt, Dm, Dm);
        add_ln<0><<<Bz, 128>>>(dt, dbuf, dec_ln1_g + i*Dm, dec_ln1_b + i*Dm, dbuf, nullptr);
        gemm8w<0><<<Dm/64, 512>>>(dbuf, dec_qkv2_w + (size_t)(i*3+0)*DD, dec_qkv2_b + (i*3+0)*Dm, dq, Dm, Dm);
        cross_attn<<<dim3(Hn, Bz), 256>>>(dq, kvf + (size_t)i*2*MD, kvf + (size_t)i*2*MD + MD, dt);
        add_ln<0><<<Bz, 128>>>(dt, dbuf, dec_ln2_g + i*Dm, dec_ln2_b + i*Dm, dbuf, nullptr);
        gemm8w<1><<<DFFz/64, 512>>>(dbuf, dec_ffn1_w + (size_t)i*Dm*DFFz, dec_ffn1_b + i*DFFz, dh, Dm, DFFz);
        gemm8w<0><<<Dm/64, 512>>>(dh, dec_ffn2_w + (size_t)i*DFFz*Dm, dec_ffn2_b + i*Dm, dt, DFFz, Dm);
        add_ln<0><<<Bz, 128>>>(dt, dbuf, dec_ln3_g + i*Dm, dec_ln3_b + i*Dm, dbuf, nullptr);
    }

    // output projection -> d_out [8,1,1000]
    gemm8w<0><<<(OUTz+63)/64, 512>>>(dbuf, out_w, out_b, (float*)d_out, Dm, OUTz);
    (void)in_sizes; (void)n_in; (void)out_size;
}